// round 11
// baseline (speedup 1.0000x reference)
#include <cuda_runtime.h>
#include <cuda_bf16.h>
#include <stdint.h>
#include <math.h>

// Problem dims (fixed)
#define BB   2
#define TT   2048
#define CC   1024
#define HH   16
#define DD   64
#define HID  256
#define FF   4096
#define MM   (BB*TT)   // 4096 rows
#define C3   (3*CC)    // fused qkv width

// ---------------- scratch (device globals; no allocation allowed) ----------------
__device__ __align__(16) float g_qkv[MM*C3];     // fused q|k|v fp32
__device__ __align__(16) float g_h [MM*HID];
__device__ __align__(16) float g_sur[MM*HH];
__device__ __align__(16) float g_y [MM*CC];
// bf16 hi/lo split activations
__device__ __align__(16) __nv_bfloat16 g_xh [MM*CC],  g_xl [MM*CC];
__device__ __align__(16) __nv_bfloat16 g_ysh[MM*CC],  g_ysl[MM*CC];
__device__ __align__(16) __nv_bfloat16 g_ynh[MM*CC],  g_ynl[MM*CC];
__device__ __align__(16) __nv_bfloat16 g_ffh[MM*FF],  g_ffl[MM*FF];
// bf16 hi/lo split weights (qkv concatenated [3C, C])
__device__ __align__(16) __nv_bfloat16 g_Wqkvh[C3*CC], g_Wqkvl[C3*CC];
__device__ __align__(16) __nv_bfloat16 g_Wm1h[HID*CC], g_Wm1l[HID*CC];
__device__ __align__(16) __nv_bfloat16 g_Wph[CC*CC],  g_Wpl[CC*CC];
__device__ __align__(16) __nv_bfloat16 g_Wfh[FF*CC],  g_Wfl[FF*CC];
__device__ __align__(16) __nv_bfloat16 g_Wch[CC*FF],  g_Wcl[CC*FF];

// ---------------- helpers ---------------------------------------------------------
__device__ __forceinline__ void split2(float v, __nv_bfloat16& h, __nv_bfloat16& l) {
    h = __float2bfloat16(v);
    l = __float2bfloat16(v - __bfloat162float(h));
}

__global__ __launch_bounds__(256) void split_kernel(
    const float* __restrict__ src, __nv_bfloat16* __restrict__ hi,
    __nv_bfloat16* __restrict__ lo, int n2)
{
    int i = blockIdx.x * 256 + threadIdx.x;
    if (i >= n2) return;
    float2 v = ((const float2*)src)[i];
    __nv_bfloat162 h, l;
    split2(v.x, h.x, l.x);
    split2(v.y, h.y, l.y);
    ((__nv_bfloat162*)hi)[i] = h;
    ((__nv_bfloat162*)lo)[i] = l;
}

// fused split of Wq|Wk|Wv into concatenated hi/lo [3C, C]
__global__ __launch_bounds__(256) void split_qkv_kernel(
    const float* __restrict__ Wq, const float* __restrict__ Wk,
    const float* __restrict__ Wv, __nv_bfloat16* __restrict__ hi,
    __nv_bfloat16* __restrict__ lo)
{
    const int seg = CC * CC / 2;
    int i = blockIdx.x * 256 + threadIdx.x;
    if (i >= 3 * seg) return;
    const float* src = (i < seg) ? Wq : (i < 2 * seg ? Wk : Wv);
    int j = (i < seg) ? i : (i < 2 * seg ? i - seg : i - 2 * seg);
    float2 v = ((const float2*)src)[j];
    __nv_bfloat162 h, l;
    split2(v.x, h.x, l.x);
    split2(v.y, h.y, l.y);
    ((__nv_bfloat162*)hi)[i] = h;
    ((__nv_bfloat162*)lo)[i] = l;
}

// fused split of Wproj, Wfc, Wcp (separate dests)
__global__ __launch_bounds__(256) void split_w3_kernel(
    const float* __restrict__ Wp, const float* __restrict__ Wf,
    const float* __restrict__ Wc,
    __nv_bfloat16* __restrict__ Wph, __nv_bfloat16* __restrict__ Wpl,
    __nv_bfloat16* __restrict__ Wfh, __nv_bfloat16* __restrict__ Wfl,
    __nv_bfloat16* __restrict__ Wch, __nv_bfloat16* __restrict__ Wcl)
{
    const int s1 = CC * CC / 2;          // Wproj
    const int s2 = FF * CC / 2;          // Wfc
    const int s3 = CC * FF / 2;          // Wcp
    int i = blockIdx.x * 256 + threadIdx.x;
    if (i >= s1 + s2 + s3) return;
    const float* src; __nv_bfloat16 *dh, *dl; int j;
    if (i < s1)           { src = Wp; dh = Wph; dl = Wpl; j = i; }
    else if (i < s1 + s2) { src = Wf; dh = Wfh; dl = Wfl; j = i - s1; }
    else                  { src = Wc; dh = Wch; dl = Wcl; j = i - s1 - s2; }
    float2 v = ((const float2*)src)[j];
    __nv_bfloat162 h, l;
    split2(v.x, h.x, l.x);
    split2(v.y, h.y, l.y);
    ((__nv_bfloat162*)dh)[j] = h;
    ((__nv_bfloat162*)dl)[j] = l;
}

__device__ __forceinline__ void cp16(void* dst, const void* src) {
    unsigned int d = (unsigned int)__cvta_generic_to_shared(dst);
    asm volatile("cp.async.cg.shared.global [%0], [%1], 16;" :: "r"(d), "l"(src));
}
__device__ __forceinline__ void cp4(void* dst, const void* src) {
    unsigned int d = (unsigned int)__cvta_generic_to_shared(dst);
    asm volatile("cp.async.ca.shared.global [%0], [%1], 4;" :: "r"(d), "l"(src));
}

__device__ __forceinline__ void mma16(float c[4], const uint32_t a[4],
                                      uint32_t b0, uint32_t b1) {
    asm volatile(
        "mma.sync.aligned.m16n8k16.row.col.f32.bf16.bf16.f32 "
        "{%0,%1,%2,%3},{%4,%5,%6,%7},{%8,%9},{%0,%1,%2,%3};"
        : "+f"(c[0]), "+f"(c[1]), "+f"(c[2]), "+f"(c[3])
        : "r"(a[0]), "r"(a[1]), "r"(a[2]), "r"(a[3]), "r"(b0), "r"(b1));
}

#define LDSM4(r, addr) \
    asm volatile("ldmatrix.sync.aligned.m8n8.x4.shared.b16 {%0,%1,%2,%3},[%4];" \
        : "=r"((r)[0]), "=r"((r)[1]), "=r"((r)[2]), "=r"((r)[3]) : "r"(addr))

// ---------------- bf16x3 tensor-core GEMM: out = epi( A[M,K] @ W[N,K]^T ) ---------
// EPI: 0 = plain, 1 = relu(acc + bias[n]), 2 = relu(acc)^2, 3 = acc + R[m,n]
// OSPLIT: 0 -> fp32 out; 1 -> bf16 hi/lo out
#define BM   128
#define BNW  128
#define BKH  32                // k elements per stage
#define STR  40                // padded smem row stride (halfs) -> 80B; conflict-free LDSM
#define STAGE_H (BM*STR)       // halfs per array per stage
#define SMEM_BYTES (2*4*STAGE_H*2)   // 81920 B

template<int EPI, int OSPLIT>
__global__ __launch_bounds__(256, 2) void bf16_gemm(
    const __nv_bfloat16* __restrict__ Ahg, const __nv_bfloat16* __restrict__ Alg,
    const __nv_bfloat16* __restrict__ Whg, const __nv_bfloat16* __restrict__ Wlg,
    const float* __restrict__ bias, const float* __restrict__ R,
    float* __restrict__ out, __nv_bfloat16* __restrict__ outh,
    __nv_bfloat16* __restrict__ outl, int M, int N, int K)
{
    extern __shared__ __nv_bfloat16 sm[];
    const int tid  = threadIdx.x;
    const int lane = tid & 31;
    const int w    = tid >> 5;
    const int g    = lane >> 2;
    const int tig  = lane & 3;
    const int wm   = w & 3;          // 4 warps along M (32 rows)
    const int wn   = w >> 2;         // 2 warps along N (64 cols)
    const int bm0  = blockIdx.y * BM;
    const int bn0  = blockIdx.x * BNW;

    const uint32_t smb = (uint32_t)__cvta_generic_to_shared(sm);
    const uint32_t lofs = (uint32_t)(((lane & 7) + ((lane >> 3) & 1) * 8) * STR
                                     + (lane >> 4) * 8);

    float acc[2][8][4];
#pragma unroll
    for (int i = 0; i < 2; i++)
#pragma unroll
        for (int j = 0; j < 8; j++)
#pragma unroll
            for (int r = 0; r < 4; r++) acc[i][j][r] = 0.f;

    const int NK = K / BKH;

    auto load_stage = [&](int s, int k0) {
        __nv_bfloat16* base = sm + s * 4 * STAGE_H;
#pragma unroll
        for (int t = 0; t < 2; t++) {
            int tsk = tid + t * 256;
            int row = tsk >> 2;
            int ch  = (tsk & 3) * 8;
            int so  = row * STR + ch;
            cp16(base + 0 * STAGE_H + so, Ahg + (size_t)(bm0 + row) * K + k0 + ch);
            cp16(base + 1 * STAGE_H + so, Alg + (size_t)(bm0 + row) * K + k0 + ch);
            cp16(base + 2 * STAGE_H + so, Whg + (size_t)(bn0 + row) * K + k0 + ch);
            cp16(base + 3 * STAGE_H + so, Wlg + (size_t)(bn0 + row) * K + k0 + ch);
        }
    };

    load_stage(0, 0);
    asm volatile("cp.async.commit_group;");

    // single barrier per k-stage: by the time a warp passes the barrier it has
    // issued all HMMAs of the previous stage (so its LDSM reads completed via
    // register dependency) -> overwriting the other stage is safe.
    for (int it = 0; it < NK; it++) {
        asm volatile("cp.async.wait_group 0;");
        __syncthreads();

        if (it + 1 < NK) {
            load_stage((it + 1) & 1, (it + 1) * BKH);
            asm volatile("cp.async.commit_group;");
        }

        const uint32_t stageB = smb + (uint32_t)((it & 1) * 4 * STAGE_H) * 2;

#pragma unroll
        for (int ks = 0; ks < BKH; ks += 16) {
            uint32_t ah[2][4], al[2][4];
#pragma unroll
            for (int i = 0; i < 2; i++) {
                uint32_t ta = stageB + 2u * ((uint32_t)((wm * 32 + i * 16) * STR + ks) + lofs);
                LDSM4(ah[i], ta);
                LDSM4(al[i], ta + 2u * STAGE_H);
            }
#pragma unroll
            for (int jp = 0; jp < 4; jp++) {
                uint32_t bh[4], bl[4];
                uint32_t tb = stageB + 2u * ((uint32_t)(2 * STAGE_H
                              + (wn * 64 + jp * 16) * STR + ks) + lofs);
                LDSM4(bh, tb);
                LDSM4(bl, tb + 2u * STAGE_H);
#pragma unroll
                for (int sub = 0; sub < 2; sub++) {
                    const int j = jp * 2 + sub;
                    uint32_t bh0 = bh[sub], bh1 = bh[sub + 2];
                    uint32_t bl0 = bl[sub], bl1 = bl[sub + 2];
#pragma unroll
                    for (int i = 0; i < 2; i++) {
                        mma16(acc[i][j], ah[i], bh0, bh1);   // hi*hi
                        mma16(acc[i][j], ah[i], bl0, bl1);   // hi*lo
                        mma16(acc[i][j], al[i], bh0, bh1);   // lo*hi
                    }
                }
            }
        }
    }

    // ---------------- epilogue ----------------
#pragma unroll
    for (int i = 0; i < 2; i++) {
        const int row0 = bm0 + wm * 32 + i * 16 + g;
        const int row1 = row0 + 8;
#pragma unroll
        for (int j = 0; j < 8; j++) {
            const int col = bn0 + wn * 64 + j * 8 + 2 * tig;
            float2 v01 = make_float2(acc[i][j][0], acc[i][j][1]);
            float2 v23 = make_float2(acc[i][j][2], acc[i][j][3]);
            if (EPI == 1) {
                float2 bb = *(const float2*)(bias + col);
                v01.x = fmaxf(v01.x + bb.x, 0.f); v01.y = fmaxf(v01.y + bb.y, 0.f);
                v23.x = fmaxf(v23.x + bb.x, 0.f); v23.y = fmaxf(v23.y + bb.y, 0.f);
            } else if (EPI == 2) {
                v01.x = fmaxf(v01.x, 0.f); v01.x *= v01.x;
                v01.y = fmaxf(v01.y, 0.f); v01.y *= v01.y;
                v23.x = fmaxf(v23.x, 0.f); v23.x *= v23.x;
                v23.y = fmaxf(v23.y, 0.f); v23.y *= v23.y;
            } else if (EPI == 3) {
                float2 r0v = *(const float2*)(R + (size_t)row0 * N + col);
                float2 r1v = *(const float2*)(R + (size_t)row1 * N + col);
                v01.x += r0v.x; v01.y += r0v.y;
                v23.x += r1v.x; v23.y += r1v.y;
            }
            if (OSPLIT) {
                __nv_bfloat162 h2, l2;
                split2(v01.x, h2.x, l2.x); split2(v01.y, h2.y, l2.y);
                *(__nv_bfloat162*)(outh + (size_t)row0 * N + col) = h2;
                *(__nv_bfloat162*)(outl + (size_t)row0 * N + col) = l2;
                split2(v23.x, h2.x, l2.x); split2(v23.y, h2.y, l2.y);
                *(__nv_bfloat162*)(outh + (size_t)row1 * N + col) = h2;
                *(__nv_bfloat162*)(outl + (size_t)row1 * N + col) = l2;
            } else {
                *(float2*)(out + (size_t)row0 * N + col) = v01;
                *(float2*)(out + (size_t)row1 * N + col) = v23;
            }
        }
    }
}

// ---------------- meta-net layer 2 + sigmoid --------------------------------------
__global__ __launch_bounds__(256) void meta2_kernel(
    const float* __restrict__ hbuf, const float* __restrict__ Wm2,
    const float* __restrict__ bm2, float* __restrict__ sur)
{
    int idx = blockIdx.x * blockDim.x + threadIdx.x;
    if (idx >= MM * HH) return;
    int m = idx / HH, h = idx % HH;
    const float* hv = hbuf + (size_t)m * HID;
    const float* w  = Wm2 + (size_t)h * HID;
    float acc = bm2[h];
#pragma unroll 8
    for (int j = 0; j < HID; j++) acc += hv[j] * w[j];
    sur[idx] = 1.f / (1.f + expf(-acc));
}

// ---------------- gated linear-attention scan (fused qkv input) -------------------
#define NSTG 4
#define SUBT 4
#define SSTEP 164

__global__ __launch_bounds__(256) void scan_kernel(
    const float* __restrict__ qkv, const float* __restrict__ sur,
    __nv_bfloat16* __restrict__ ysh, __nv_bfloat16* __restrict__ ysl)
{
    __shared__ float ring[NSTG][SUBT][SSTEP];

    const int bid = blockIdx.x;
    const int b  = bid / (HH * 2);
    const int rem = bid % (HH * 2);
    const int h  = rem >> 1;
    const int eh = rem & 1;
    const int tid = threadIdx.x;
    const int dg  = tid & 7;
    const int el  = tid >> 3;
    const int e   = eh * 32 + el;
    const int d0  = dg * 8;

    const size_t baseIn  = (size_t)b * TT * C3 + (size_t)h * DD;
    const size_t baseOut = (size_t)b * TT * CC + (size_t)h * DD;
    const size_t surBase = (size_t)b * TT * HH + h;

    float s[8];
#pragma unroll
    for (int i = 0; i < 8; i++) s[i] = 0.f;

    auto fill = [&](int stg, int t0) {
        if (tid < 160) {
            int st = tid / 40, c = tid % 40;
            int t = t0 + st;
            if (t < TT) {
                size_t off = baseIn + (size_t)t * C3;
                if (c < 16)
                    cp16(&ring[stg][st][c * 4], qkv + off + CC + c * 4);
                else if (c < 32)
                    cp16(&ring[stg][st][64 + (c - 16) * 4], qkv + off + (c - 16) * 4);
                else
                    cp16(&ring[stg][st][128 + (c - 32) * 4],
                         qkv + off + 2 * CC + eh * 32 + (c - 32) * 4);
            }
        } else if (tid < 164) {
            int st = tid - 160;
            int t = t0 + st;
            if (t < TT)
                cp4(&ring[stg][st][160], sur + surBase + (size_t)t * HH);
        }
    };

#pragma unroll
    for (int i = 0; i < NSTG; i++) {
        fill(i, i * SUBT);
        asm volatile("cp.async.commit_group;");
    }

    const int NB = TT / SUBT;
    for (int ib = 0; ib < NB; ib++) {
        asm volatile("cp.async.wait_group %0;" :: "n"(NSTG - 1));
        __syncthreads();
        const int stg = ib & (NSTG - 1);

#pragma unroll
        for (int st = 0; st < SUBT; st++) {
            const float* row = ring[stg][st];
            const float gt = row[160];
            const float ve = row[128 + el];
            const float dt = 1.f - gt;
            const float c  = gt * ve;
            float accum = 0.f;
#pragma unroll
            for (int i = 0; i < 8; i++) {
                float kv = row[d0 + i];
                float qv = row[64 + d0 + i];
                s[i] = s[i] * dt + c * kv;
                accum = fmaf(qv, s[i], accum);
            }
            accum += __shfl_xor_sync(0xFFFFFFFF, accum, 1);
            accum += __shfl_xor_sync(0xFFFFFFFF, accum, 2);
            accum += __shfl_xor_sync(0xFFFFFFFF, accum, 4);
            if (dg == 0) {
                const int t = ib * SUBT + st;
                const size_t off = baseOut + (size_t)t * CC + e;
                __nv_bfloat16 hh, ll;
                split2(accum, hh, ll);
                ysh[off] = hh;
                ysl[off] = ll;
            }
        }
        __syncthreads();
        fill(stg, (ib + NSTG) * SUBT);
        asm volatile("cp.async.commit_group;");
    }
}

// ---------------- RMSNorm -> bf16 hi/lo -------------------------------------------
__global__ __launch_bounds__(256) void rmsnorm_kernel(
    const float* __restrict__ y, __nv_bfloat16* __restrict__ ynh,
    __nv_bfloat16* __restrict__ ynl)
{
    const int row = blockIdx.x;
    const float* p = y + (size_t)row * CC;
    float ss = 0.f;
    for (int i = threadIdx.x; i < CC; i += 256) { float u = p[i]; ss += u * u; }

    __shared__ float red[8];
    for (int o = 16; o > 0; o >>= 1) ss += __shfl_xor_sync(0xFFFFFFFF, ss, o);
    if ((threadIdx.x & 31) == 0) red[threadIdx.x >> 5] = ss;
    __syncthreads();
    if (threadIdx.x < 8) {
        ss = red[threadIdx.x];
        for (int o = 4; o > 0; o >>= 1) ss += __shfl_xor_sync(0xFF, ss, o);
        if (threadIdx.x == 0) red[0] = ss;
    }
    __syncthreads();
    const float inv = rsqrtf(red[0] * (1.f / CC) + 1.1920928955078125e-07f);
    for (int i = threadIdx.x; i < CC; i += 256) {
        float u = p[i] * inv;
        __nv_bfloat16 hh, ll;
        split2(u, hh, ll);
        ynh[(size_t)row * CC + i] = hh;
        ynl[(size_t)row * CC + i] = ll;
    }
}

// ---------------- host driver -----------------------------------------------------
#define SYM(p, s) cudaGetSymbolAddress((void**)&p, s)

extern "C" void kernel_launch(void* const* d_in, const int* in_sizes, int n_in,
                              void* d_out, int out_size)
{
    const float* x     = (const float*)d_in[0];
    const float* Wq    = (const float*)d_in[1];
    const float* Wk    = (const float*)d_in[2];
    const float* Wv    = (const float*)d_in[3];
    const float* Wm1   = (const float*)d_in[4];
    const float* bm1   = (const float*)d_in[5];
    const float* Wm2   = (const float*)d_in[6];
    const float* bm2   = (const float*)d_in[7];
    const float* Wproj = (const float*)d_in[8];
    const float* Wfc   = (const float*)d_in[9];
    const float* Wcp   = (const float*)d_in[10];
    float* out = (float*)d_out;

    float *pqkv, *ph, *psur, *py;
    __nv_bfloat16 *pxh, *pxl, *pysh, *pysl, *pynh, *pynl, *pffh, *pffl;
    __nv_bfloat16 *pWqkvh, *pWqkvl, *pWm1h, *pWm1l;
    __nv_bfloat16 *pWph, *pWpl, *pWfh, *pWfl, *pWch, *pWcl;

    SYM(pqkv, g_qkv); SYM(ph, g_h); SYM(psur, g_sur); SYM(py, g_y);
    SYM(pxh, g_xh); SYM(pxl, g_xl);
    SYM(pysh, g_ysh); SYM(pysl, g_ysl);
    SYM(pynh, g_ynh); SYM(pynl, g_ynl);
    SYM(pffh, g_ffh); SYM(pffl, g_ffl);
    SYM(pWqkvh, g_Wqkvh); SYM(pWqkvl, g_Wqkvl);
    SYM(pWm1h, g_Wm1h); SYM(pWm1l, g_Wm1l);
    SYM(pWph, g_Wph); SYM(pWpl, g_Wpl);
    SYM(pWfh, g_Wfh); SYM(pWfl, g_Wfl);
    SYM(pWch, g_Wch); SYM(pWcl, g_Wcl);

    cudaFuncSetAttribute(bf16_gemm<0,0>, cudaFuncAttributeMaxDynamicSharedMemorySize, SMEM_BYTES);
    cudaFuncSetAttribute(bf16_gemm<1,0>, cudaFuncAttributeMaxDynamicSharedMemorySize, SMEM_BYTES);
    cudaFuncSetAttribute(bf16_gemm<2,1>, cudaFuncAttributeMaxDynamicSharedMemorySize, SMEM_BYTES);
    cudaFuncSetAttribute(bf16_gemm<3,0>, cudaFuncAttributeMaxDynamicSharedMemorySize, SMEM_BYTES);

    dim3 thr(256);
    dim3 gQKV(C3  / BNW, MM / BM);   // 24 x 32 = 768 CTAs
    dim3 gC  (CC  / BNW, MM / BM);
    dim3 gH  (HID / BNW, MM / BM);
    dim3 gFF (FF  / BNW, MM / BM);

    // 0: x split
    split_kernel<<<(MM * CC / 2 + 255) / 256, thr>>>(x, pxh, pxl, MM * CC / 2);
    // 1: fused QKV weight split
    split_qkv_kernel<<<(3 * CC * CC / 2 + 255) / 256, thr>>>(Wq, Wk, Wv, pWqkvh, pWqkvl);
    // 2: Wm1 split
    split_kernel<<<(HID * CC / 2 + 255) / 256, thr>>>(Wm1, pWm1h, pWm1l, HID * CC / 2);

    // 3: fused QKV projection -> qkv fp32
    bf16_gemm<0,0><<<gQKV, thr, SMEM_BYTES>>>(pxh, pxl, pWqkvh, pWqkvl, nullptr, nullptr,
                                              pqkv, nullptr, nullptr, MM, C3, CC);

    // 4: meta net layer 1
    bf16_gemm<1,0><<<gH, thr, SMEM_BYTES>>>(pxh, pxl, pWm1h, pWm1l, bm1, nullptr,
                                            ph, nullptr, nullptr, MM, HID, CC);
    // 5: meta net layer 2 + sigmoid
    meta2_kernel<<<(MM * HH + 255) / 256, thr>>>(ph, Wm2, bm2, psur);

    // 6: gated linear-attention scan -> ys (bf16 hi/lo)
    scan_kernel<<<BB * HH * 2, 256>>>(pqkv, psur, pysh, pysl);

    // 7: fused remaining weight splits
    {
        int tot = CC * CC / 2 + FF * CC / 2 + CC * FF / 2;
        split_w3_kernel<<<(tot + 255) / 256, thr>>>(Wproj, Wfc, Wcp,
                                                    pWph, pWpl, pWfh, pWfl, pWch, pWcl);
    }

    // 8: output projection (fp32 y, needed for residual)
    bf16_gemm<0,0><<<gC, thr, SMEM_BYTES>>>(pysh, pysl, pWph, pWpl, nullptr, nullptr,
                                            py, nullptr, nullptr, MM, CC, CC);

    // 9: RMSNorm -> yn (bf16 hi/lo)
    rmsnorm_kernel<<<MM, thr>>>(py, pynh, pynl);

    // 10: MLP up: ff = relu(yn Wfc^T)^2 (bf16 hi/lo)
    bf16_gemm<2,1><<<gFF, thr, SMEM_BYTES>>>(pynh, pynl, pWfh, pWfl, nullptr, nullptr,
                                             nullptr, pffh, pffl, MM, FF, CC);
    // 11: MLP down + residual: out = y + ff Wcp^T
    bf16_gemm<3,0><<<gC, thr, SMEM_BYTES>>>(pffh, pffl, pWch, pWcl, nullptr, py,
                                            out, nullptr, nullptr, MM, CC, FF);
}

// round 13
// speedup vs baseline: 1.0205x; 1.0205x over previous
#include <cuda_runtime.h>
#include <cuda_bf16.h>
#include <stdint.h>
#include <math.h>

// Problem dims (fixed)
#define BB   2
#define TT   2048
#define CC   1024
#define HH   16
#define DD   64
#define HID  256
#define FF   4096
#define MM   (BB*TT)   // 4096 rows
#define C3   (3*CC)    // fused qkv width

// ---------------- scratch (device globals; no allocation allowed) ----------------
__device__ __align__(16) float g_qkv[MM*C3];     // fused q|k|v fp32
__device__ __align__(16) float g_h [MM*HID];
__device__ __align__(16) float g_sur[MM*HH];
__device__ __align__(16) float g_y [MM*CC];
// bf16 hi/lo split activations
__device__ __align__(16) __nv_bfloat16 g_xh [MM*CC],  g_xl [MM*CC];
__device__ __align__(16) __nv_bfloat16 g_ysh[MM*CC],  g_ysl[MM*CC];
__device__ __align__(16) __nv_bfloat16 g_ynh[MM*CC],  g_ynl[MM*CC];
__device__ __align__(16) __nv_bfloat16 g_ffh[MM*FF],  g_ffl[MM*FF];
// bf16 hi/lo split weights (qkv concatenated [3C, C])
__device__ __align__(16) __nv_bfloat16 g_Wqkvh[C3*CC], g_Wqkvl[C3*CC];
__device__ __align__(16) __nv_bfloat16 g_Wm1h[HID*CC], g_Wm1l[HID*CC];
__device__ __align__(16) __nv_bfloat16 g_Wph[CC*CC],  g_Wpl[CC*CC];
__device__ __align__(16) __nv_bfloat16 g_Wfh[FF*CC],  g_Wfl[FF*CC];
__device__ __align__(16) __nv_bfloat16 g_Wch[CC*FF],  g_Wcl[CC*FF];

// ---------------- helpers ---------------------------------------------------------
__device__ __forceinline__ void split2(float v, __nv_bfloat16& h, __nv_bfloat16& l) {
    h = __float2bfloat16(v);
    l = __float2bfloat16(v - __bfloat162float(h));
}

__global__ __launch_bounds__(256) void split_kernel(
    const float* __restrict__ src, __nv_bfloat16* __restrict__ hi,
    __nv_bfloat16* __restrict__ lo, int n2)
{
    int i = blockIdx.x * 256 + threadIdx.x;
    if (i >= n2) return;
    float2 v = ((const float2*)src)[i];
    __nv_bfloat162 h, l;
    split2(v.x, h.x, l.x);
    split2(v.y, h.y, l.y);
    ((__nv_bfloat162*)hi)[i] = h;
    ((__nv_bfloat162*)lo)[i] = l;
}

// fused split of Wq|Wk|Wv into concatenated hi/lo [3C, C]
__global__ __launch_bounds__(256) void split_qkv_kernel(
    const float* __restrict__ Wq, const float* __restrict__ Wk,
    const float* __restrict__ Wv, __nv_bfloat16* __restrict__ hi,
    __nv_bfloat16* __restrict__ lo)
{
    const int seg = CC * CC / 2;
    int i = blockIdx.x * 256 + threadIdx.x;
    if (i >= 3 * seg) return;
    const float* src = (i < seg) ? Wq : (i < 2 * seg ? Wk : Wv);
    int j = (i < seg) ? i : (i < 2 * seg ? i - seg : i - 2 * seg);
    float2 v = ((const float2*)src)[j];
    __nv_bfloat162 h, l;
    split2(v.x, h.x, l.x);
    split2(v.y, h.y, l.y);
    ((__nv_bfloat162*)hi)[i] = h;
    ((__nv_bfloat162*)lo)[i] = l;
}

// fused split of Wproj, Wfc, Wcp (separate dests)
__global__ __launch_bounds__(256) void split_w3_kernel(
    const float* __restrict__ Wp, const float* __restrict__ Wf,
    const float* __restrict__ Wc,
    __nv_bfloat16* __restrict__ Wph, __nv_bfloat16* __restrict__ Wpl,
    __nv_bfloat16* __restrict__ Wfh, __nv_bfloat16* __restrict__ Wfl,
    __nv_bfloat16* __restrict__ Wch, __nv_bfloat16* __restrict__ Wcl)
{
    const int s1 = CC * CC / 2;          // Wproj
    const int s2 = FF * CC / 2;          // Wfc
    const int s3 = CC * FF / 2;          // Wcp
    int i = blockIdx.x * 256 + threadIdx.x;
    if (i >= s1 + s2 + s3) return;
    const float* src; __nv_bfloat16 *dh, *dl; int j;
    if (i < s1)           { src = Wp; dh = Wph; dl = Wpl; j = i; }
    else if (i < s1 + s2) { src = Wf; dh = Wfh; dl = Wfl; j = i - s1; }
    else                  { src = Wc; dh = Wch; dl = Wcl; j = i - s1 - s2; }
    float2 v = ((const float2*)src)[j];
    __nv_bfloat162 h, l;
    split2(v.x, h.x, l.x);
    split2(v.y, h.y, l.y);
    ((__nv_bfloat162*)dh)[j] = h;
    ((__nv_bfloat162*)dl)[j] = l;
}

__device__ __forceinline__ void cp16(void* dst, const void* src) {
    unsigned int d = (unsigned int)__cvta_generic_to_shared(dst);
    asm volatile("cp.async.cg.shared.global [%0], [%1], 16;" :: "r"(d), "l"(src));
}
__device__ __forceinline__ void cp4(void* dst, const void* src) {
    unsigned int d = (unsigned int)__cvta_generic_to_shared(dst);
    asm volatile("cp.async.ca.shared.global [%0], [%1], 4;" :: "r"(d), "l"(src));
}

__device__ __forceinline__ void mma16(float c[4], const uint32_t a[4],
                                      uint32_t b0, uint32_t b1) {
    asm volatile(
        "mma.sync.aligned.m16n8k16.row.col.f32.bf16.bf16.f32 "
        "{%0,%1,%2,%3},{%4,%5,%6,%7},{%8,%9},{%0,%1,%2,%3};"
        : "+f"(c[0]), "+f"(c[1]), "+f"(c[2]), "+f"(c[3])
        : "r"(a[0]), "r"(a[1]), "r"(a[2]), "r"(a[3]), "r"(b0), "r"(b1));
}

#define LDSM4(r, addr) \
    asm volatile("ldmatrix.sync.aligned.m8n8.x4.shared.b16 {%0,%1,%2,%3},[%4];" \
        : "=r"((r)[0]), "=r"((r)[1]), "=r"((r)[2]), "=r"((r)[3]) : "r"(addr))

// ---------------- bf16x3 tensor-core GEMM: out = epi( A[M,K] @ W[N,K]^T ) ---------
// EPI: 0 = plain, 1 = relu(acc + bias[n]), 2 = relu(acc)^2, 3 = acc + R[m,n]
// OSPLIT: 0 -> fp32 out; 1 -> bf16 hi/lo out
#define BM   128
#define BNW  128
#define BKH  32                // k elements per stage
#define STR  40                // padded smem row stride (halfs) -> 80B; conflict-free LDSM
#define STAGE_H (BM*STR)       // halfs per array per stage
#define SMEM_BYTES (2*4*STAGE_H*2)   // 81920 B

template<int EPI, int OSPLIT>
__global__ __launch_bounds__(256, 2) void bf16_gemm(
    const __nv_bfloat16* __restrict__ Ahg, const __nv_bfloat16* __restrict__ Alg,
    const __nv_bfloat16* __restrict__ Whg, const __nv_bfloat16* __restrict__ Wlg,
    const float* __restrict__ bias, const float* __restrict__ R,
    float* __restrict__ out, __nv_bfloat16* __restrict__ outh,
    __nv_bfloat16* __restrict__ outl, int M, int N, int K)
{
    extern __shared__ __nv_bfloat16 sm[];
    const int tid  = threadIdx.x;
    const int lane = tid & 31;
    const int w    = tid >> 5;
    const int g    = lane >> 2;
    const int tig  = lane & 3;
    const int wm   = w & 3;          // 4 warps along M (32 rows)
    const int wn   = w >> 2;         // 2 warps along N (64 cols)
    const int bm0  = blockIdx.y * BM;
    const int bn0  = blockIdx.x * BNW;

    const uint32_t smb = (uint32_t)__cvta_generic_to_shared(sm);
    const uint32_t lofs = (uint32_t)(((lane & 7) + ((lane >> 3) & 1) * 8) * STR
                                     + (lane >> 4) * 8);

    float acc[2][8][4];
#pragma unroll
    for (int i = 0; i < 2; i++)
#pragma unroll
        for (int j = 0; j < 8; j++)
#pragma unroll
            for (int r = 0; r < 4; r++) acc[i][j][r] = 0.f;

    const int NK = K / BKH;

    auto load_stage = [&](int s, int k0) {
        __nv_bfloat16* base = sm + s * 4 * STAGE_H;
#pragma unroll
        for (int t = 0; t < 2; t++) {
            int tsk = tid + t * 256;
            int row = tsk >> 2;
            int ch  = (tsk & 3) * 8;
            int so  = row * STR + ch;
            cp16(base + 0 * STAGE_H + so, Ahg + (size_t)(bm0 + row) * K + k0 + ch);
            cp16(base + 1 * STAGE_H + so, Alg + (size_t)(bm0 + row) * K + k0 + ch);
            cp16(base + 2 * STAGE_H + so, Whg + (size_t)(bn0 + row) * K + k0 + ch);
            cp16(base + 3 * STAGE_H + so, Wlg + (size_t)(bn0 + row) * K + k0 + ch);
        }
    };

    load_stage(0, 0);
    asm volatile("cp.async.commit_group;");

    for (int it = 0; it < NK; it++) {
        asm volatile("cp.async.wait_group 0;");
        __syncthreads();

        if (it + 1 < NK) {
            load_stage((it + 1) & 1, (it + 1) * BKH);
            asm volatile("cp.async.commit_group;");
        }

        const uint32_t stageB = smb + (uint32_t)((it & 1) * 4 * STAGE_H) * 2;

        // B-fragment loader (jp-indexed), writes into ping-pong buffers
        auto loadB = [&](int ksv, int jp, uint32_t bh[4], uint32_t bl[4]) {
            uint32_t tb = stageB + 2u * ((uint32_t)(2 * STAGE_H
                          + (wn * 64 + jp * 16) * STR + ksv) + lofs);
            LDSM4(bh, tb);
            LDSM4(bl, tb + 2u * STAGE_H);
        };

#pragma unroll
        for (int ks = 0; ks < BKH; ks += 16) {
            uint32_t ah[2][4], al[2][4];
#pragma unroll
            for (int i = 0; i < 2; i++) {
                uint32_t ta = stageB + 2u * ((uint32_t)((wm * 32 + i * 16) * STR + ks) + lofs);
                LDSM4(ah[i], ta);
                LDSM4(al[i], ta + 2u * STAGE_H);
            }
            // software-pipelined B fragments: one-jp lookahead (ping-pong)
            uint32_t bhv[2][4], blv[2][4];
            loadB(ks, 0, bhv[0], blv[0]);
#pragma unroll
            for (int jp = 0; jp < 4; jp++) {
                const int cur = jp & 1;
                if (jp < 3) loadB(ks, jp + 1, bhv[cur ^ 1], blv[cur ^ 1]);
#pragma unroll
                for (int sub = 0; sub < 2; sub++) {
                    const int j = jp * 2 + sub;
                    const uint32_t b0h = bhv[cur][sub], b1h = bhv[cur][sub + 2];
                    const uint32_t b0l = blv[cur][sub], b1l = blv[cur][sub + 2];
                    // term-paired order: same-acc RAW chains get distance 2
                    mma16(acc[0][j], ah[0], b0h, b1h);   // hi*hi (i=0)
                    mma16(acc[1][j], ah[1], b0h, b1h);   // hi*hi (i=1)
                    mma16(acc[0][j], ah[0], b0l, b1l);   // hi*lo (i=0)
                    mma16(acc[1][j], ah[1], b0l, b1l);   // hi*lo (i=1)
                    mma16(acc[0][j], al[0], b0h, b1h);   // lo*hi (i=0)
                    mma16(acc[1][j], al[1], b0h, b1h);   // lo*hi (i=1)
                }
            }
        }
    }

    // ---------------- epilogue ----------------
#pragma unroll
    for (int i = 0; i < 2; i++) {
        const int row0 = bm0 + wm * 32 + i * 16 + g;
        const int row1 = row0 + 8;
#pragma unroll
        for (int j = 0; j < 8; j++) {
            const int col = bn0 + wn * 64 + j * 8 + 2 * tig;
            float2 v01 = make_float2(acc[i][j][0], acc[i][j][1]);
            float2 v23 = make_float2(acc[i][j][2], acc[i][j][3]);
            if (EPI == 1) {
                float2 bb = *(const float2*)(bias + col);
                v01.x = fmaxf(v01.x + bb.x, 0.f); v01.y = fmaxf(v01.y + bb.y, 0.f);
                v23.x = fmaxf(v23.x + bb.x, 0.f); v23.y = fmaxf(v23.y + bb.y, 0.f);
            } else if (EPI == 2) {
                v01.x = fmaxf(v01.x, 0.f); v01.x *= v01.x;
                v01.y = fmaxf(v01.y, 0.f); v01.y *= v01.y;
                v23.x = fmaxf(v23.x, 0.f); v23.x *= v23.x;
                v23.y = fmaxf(v23.y, 0.f); v23.y *= v23.y;
            } else if (EPI == 3) {
                float2 r0v = *(const float2*)(R + (size_t)row0 * N + col);
                float2 r1v = *(const float2*)(R + (size_t)row1 * N + col);
                v01.x += r0v.x; v01.y += r0v.y;
                v23.x += r1v.x; v23.y += r1v.y;
            }
            if (OSPLIT) {
                __nv_bfloat162 h2, l2;
                split2(v01.x, h2.x, l2.x); split2(v01.y, h2.y, l2.y);
                *(__nv_bfloat162*)(outh + (size_t)row0 * N + col) = h2;
                *(__nv_bfloat162*)(outl + (size_t)row0 * N + col) = l2;
                split2(v23.x, h2.x, l2.x); split2(v23.y, h2.y, l2.y);
                *(__nv_bfloat162*)(outh + (size_t)row1 * N + col) = h2;
                *(__nv_bfloat162*)(outl + (size_t)row1 * N + col) = l2;
            } else {
                *(float2*)(out + (size_t)row0 * N + col) = v01;
                *(float2*)(out + (size_t)row1 * N + col) = v23;
            }
        }
    }
}

// ---------------- meta-net layer 2 + sigmoid --------------------------------------
__global__ __launch_bounds__(256) void meta2_kernel(
    const float* __restrict__ hbuf, const float* __restrict__ Wm2,
    const float* __restrict__ bm2, float* __restrict__ sur)
{
    int idx = blockIdx.x * blockDim.x + threadIdx.x;
    if (idx >= MM * HH) return;
    int m = idx / HH, h = idx % HH;
    const float* hv = hbuf + (size_t)m * HID;
    const float* w  = Wm2 + (size_t)h * HID;
    float acc = bm2[h];
#pragma unroll 8
    for (int j = 0; j < HID; j++) acc += hv[j] * w[j];
    sur[idx] = 1.f / (1.f + expf(-acc));
}

// ---------------- gated linear-attention scan (fused qkv input) -------------------
#define NSTG 4
#define SUBT 4
#define SSTEP 164

__global__ __launch_bounds__(256) void scan_kernel(
    const float* __restrict__ qkv, const float* __restrict__ sur,
    __nv_bfloat16* __restrict__ ysh, __nv_bfloat16* __restrict__ ysl)
{
    __shared__ float ring[NSTG][SUBT][SSTEP];

    const int bid = blockIdx.x;
    const int b  = bid / (HH * 2);
    const int rem = bid % (HH * 2);
    const int h  = rem >> 1;
    const int eh = rem & 1;
    const int tid = threadIdx.x;
    const int dg  = tid & 7;
    const int el  = tid >> 3;
    const int e   = eh * 32 + el;
    const int d0  = dg * 8;

    const size_t baseIn  = (size_t)b * TT * C3 + (size_t)h * DD;
    const size_t baseOut = (size_t)b * TT * CC + (size_t)h * DD;
    const size_t surBase = (size_t)b * TT * HH + h;

    float s[8];
#pragma unroll
    for (int i = 0; i < 8; i++) s[i] = 0.f;

    auto fill = [&](int stg, int t0) {
        if (tid < 160) {
            int st = tid / 40, c = tid % 40;
            int t = t0 + st;
            if (t < TT) {
                size_t off = baseIn + (size_t)t * C3;
                if (c < 16)
                    cp16(&ring[stg][st][c * 4], qkv + off + CC + c * 4);
                else if (c < 32)
                    cp16(&ring[stg][st][64 + (c - 16) * 4], qkv + off + (c - 16) * 4);
                else
                    cp16(&ring[stg][st][128 + (c - 32) * 4],
                         qkv + off + 2 * CC + eh * 32 + (c - 32) * 4);
            }
        } else if (tid < 164) {
            int st = tid - 160;
            int t = t0 + st;
            if (t < TT)
                cp4(&ring[stg][st][160], sur + surBase + (size_t)t * HH);
        }
    };

#pragma unroll
    for (int i = 0; i < NSTG; i++) {
        fill(i, i * SUBT);
        asm volatile("cp.async.commit_group;");
    }

    const int NB = TT / SUBT;
    for (int ib = 0; ib < NB; ib++) {
        asm volatile("cp.async.wait_group %0;" :: "n"(NSTG - 1));
        __syncthreads();
        const int stg = ib & (NSTG - 1);

#pragma unroll
        for (int st = 0; st < SUBT; st++) {
            const float* row = ring[stg][st];
            const float gt = row[160];
            const float ve = row[128 + el];
            const float dt = 1.f - gt;
            const float c  = gt * ve;
            float accum = 0.f;
#pragma unroll
            for (int i = 0; i < 8; i++) {
                float kv = row[d0 + i];
                float qv = row[64 + d0 + i];
                s[i] = s[i] * dt + c * kv;
                accum = fmaf(qv, s[i], accum);
            }
            accum += __shfl_xor_sync(0xFFFFFFFF, accum, 1);
            accum += __shfl_xor_sync(0xFFFFFFFF, accum, 2);
            accum += __shfl_xor_sync(0xFFFFFFFF, accum, 4);
            if (dg == 0) {
                const int t = ib * SUBT + st;
                const size_t off = baseOut + (size_t)t * CC + e;
                __nv_bfloat16 hh, ll;
                split2(accum, hh, ll);
                ysh[off] = hh;
                ysl[off] = ll;
            }
        }
        __syncthreads();
        fill(stg, (ib + NSTG) * SUBT);
        asm volatile("cp.async.commit_group;");
    }
}

// ---------------- RMSNorm -> bf16 hi/lo -------------------------------------------
__global__ __launch_bounds__(256) void rmsnorm_kernel(
    const float* __restrict__ y, __nv_bfloat16* __restrict__ ynh,
    __nv_bfloat16* __restrict__ ynl)
{
    const int row = blockIdx.x;
    const float* p = y + (size_t)row * CC;
    float ss = 0.f;
    for (int i = threadIdx.x; i < CC; i += 256) { float u = p[i]; ss += u * u; }

    __shared__ float red[8];
    for (int o = 16; o > 0; o >>= 1) ss += __shfl_xor_sync(0xFFFFFFFF, ss, o);
    if ((threadIdx.x & 31) == 0) red[threadIdx.x >> 5] = ss;
    __syncthreads();
    if (threadIdx.x < 8) {
        ss = red[threadIdx.x];
        for (int o = 4; o > 0; o >>= 1) ss += __shfl_xor_sync(0xFF, ss, o);
        if (threadIdx.x == 0) red[0] = ss;
    }
    __syncthreads();
    const float inv = rsqrtf(red[0] * (1.f / CC) + 1.1920928955078125e-07f);
    for (int i = threadIdx.x; i < CC; i += 256) {
        float u = p[i] * inv;
        __nv_bfloat16 hh, ll;
        split2(u, hh, ll);
        ynh[(size_t)row * CC + i] = hh;
        ynl[(size_t)row * CC + i] = ll;
    }
}

// ---------------- host driver -----------------------------------------------------
#define SYM(p, s) cudaGetSymbolAddress((void**)&p, s)

extern "C" void kernel_launch(void* const* d_in, const int* in_sizes, int n_in,
                              void* d_out, int out_size)
{
    const float* x     = (const float*)d_in[0];
    const float* Wq    = (const float*)d_in[1];
    const float* Wk    = (const float*)d_in[2];
    const float* Wv    = (const float*)d_in[3];
    const float* Wm1   = (const float*)d_in[4];
    const float* bm1   = (const float*)d_in[5];
    const float* Wm2   = (const float*)d_in[6];
    const float* bm2   = (const float*)d_in[7];
    const float* Wproj = (const float*)d_in[8];
    const float* Wfc   = (const float*)d_in[9];
    const float* Wcp   = (const float*)d_in[10];
    float* out = (float*)d_out;

    float *pqkv, *ph, *psur, *py;
    __nv_bfloat16 *pxh, *pxl, *pysh, *pysl, *pynh, *pynl, *pffh, *pffl;
    __nv_bfloat16 *pWqkvh, *pWqkvl, *pWm1h, *pWm1l;
    __nv_bfloat16 *pWph, *pWpl, *pWfh, *pWfl, *pWch, *pWcl;

    SYM(pqkv, g_qkv); SYM(ph, g_h); SYM(psur, g_sur); SYM(py, g_y);
    SYM(pxh, g_xh); SYM(pxl, g_xl);
    SYM(pysh, g_ysh); SYM(pysl, g_ysl);
    SYM(pynh, g_ynh); SYM(pynl, g_ynl);
    SYM(pffh, g_ffh); SYM(pffl, g_ffl);
    SYM(pWqkvh, g_Wqkvh); SYM(pWqkvl, g_Wqkvl);
    SYM(pWm1h, g_Wm1h); SYM(pWm1l, g_Wm1l);
    SYM(pWph, g_Wph); SYM(pWpl, g_Wpl);
    SYM(pWfh, g_Wfh); SYM(pWfl, g_Wfl);
    SYM(pWch, g_Wch); SYM(pWcl, g_Wcl);

    cudaFuncSetAttribute(bf16_gemm<0,0>, cudaFuncAttributeMaxDynamicSharedMemorySize, SMEM_BYTES);
    cudaFuncSetAttribute(bf16_gemm<1,0>, cudaFuncAttributeMaxDynamicSharedMemorySize, SMEM_BYTES);
    cudaFuncSetAttribute(bf16_gemm<2,1>, cudaFuncAttributeMaxDynamicSharedMemorySize, SMEM_BYTES);
    cudaFuncSetAttribute(bf16_gemm<3,0>, cudaFuncAttributeMaxDynamicSharedMemorySize, SMEM_BYTES);

    dim3 thr(256);
    dim3 gQKV(C3  / BNW, MM / BM);   // 24 x 32 = 768 CTAs
    dim3 gC  (CC  / BNW, MM / BM);
    dim3 gH  (HID / BNW, MM / BM);
    dim3 gFF (FF  / BNW, MM / BM);

    // 0: x split
    split_kernel<<<(MM * CC / 2 + 255) / 256, thr>>>(x, pxh, pxl, MM * CC / 2);
    // 1: fused QKV weight split
    split_qkv_kernel<<<(3 * CC * CC / 2 + 255) / 256, thr>>>(Wq, Wk, Wv, pWqkvh, pWqkvl);
    // 2: Wm1 split
    split_kernel<<<(HID * CC / 2 + 255) / 256, thr>>>(Wm1, pWm1h, pWm1l, HID * CC / 2);

    // 3: fused QKV projection -> qkv fp32
    bf16_gemm<0,0><<<gQKV, thr, SMEM_BYTES>>>(pxh, pxl, pWqkvh, pWqkvl, nullptr, nullptr,
                                              pqkv, nullptr, nullptr, MM, C3, CC);

    // 4: meta net layer 1
    bf16_gemm<1,0><<<gH, thr, SMEM_BYTES>>>(pxh, pxl, pWm1h, pWm1l, bm1, nullptr,
                                            ph, nullptr, nullptr, MM, HID, CC);
    // 5: meta net layer 2 + sigmoid
    meta2_kernel<<<(MM * HH + 255) / 256, thr>>>(ph, Wm2, bm2, psur);

    // 6: gated linear-attention scan -> ys (bf16 hi/lo)
    scan_kernel<<<BB * HH * 2, 256>>>(pqkv, psur, pysh, pysl);

    // 7: fused remaining weight splits
    {
        int tot = CC * CC / 2 + FF * CC / 2 + CC * FF / 2;
        split_w3_kernel<<<(tot + 255) / 256, thr>>>(Wproj, Wfc, Wcp,
                                                    pWph, pWpl, pWfh, pWfl, pWch, pWcl);
    }

    // 8: output projection (fp32 y, needed for residual)
    bf16_gemm<0,0><<<gC, thr, SMEM_BYTES>>>(pysh, pysl, pWph, pWpl, nullptr, nullptr,
                                            py, nullptr, nullptr, MM, CC, CC);

    // 9: RMSNorm -> yn (bf16 hi/lo)
    rmsnorm_kernel<<<MM, thr>>>(py, pynh, pynl);

    // 10: MLP up: ff = relu(yn Wfc^T)^2 (bf16 hi/lo)
    bf16_gemm<2,1><<<gFF, thr, SMEM_BYTES>>>(pynh, pynl, pWfh, pWfl, nullptr, nullptr,
                                             nullptr, pffh, pffl, MM, FF, CC);
    // 11: MLP down + residual: out = y + ff Wcp^T
    bf16_gemm<3,0><<<gC, thr, SMEM_BYTES>>>(pffh, pffl, pWch, pWcl, nullptr, py,
                                            out, nullptr, nullptr, MM, CC, FF);
}

// round 14
// speedup vs baseline: 1.3485x; 1.3213x over previous
#include <cuda_runtime.h>
#include <cuda_fp16.h>
#include <stdint.h>
#include <math.h>

// Problem dims (fixed)
#define BB   2
#define TT   2048
#define CC   1024
#define HH   16
#define DD   64
#define HID  256
#define FF   4096
#define MM   (BB*TT)   // 4096 rows
#define C3   (3*CC)    // fused qkv width

#define WSCALE   32.0f
#define INV_WSCALE (1.0f/32.0f)

// ---------------- scratch (device globals; no allocation allowed) ----------------
__device__ __align__(16) float g_qkv[MM*C3];     // fused q|k|v fp32
__device__ __align__(16) float g_h [MM*HID];
__device__ __align__(16) float g_sur[MM*HH];
__device__ __align__(16) float g_y [MM*CC];
// fp16 activations (hi only; dropped-lo error = 2^-12 random, by design)
__device__ __align__(16) __half g_xh [MM*CC];
__device__ __align__(16) __half g_ysh[MM*CC];
__device__ __align__(16) __half g_ynh[MM*CC];
__device__ __align__(16) __half g_ffh[MM*FF];
// fp16 hi/lo split weights, pre-scaled by WSCALE (qkv concatenated [3C, C])
__device__ __align__(16) __half g_Wqkvh[C3*CC], g_Wqkvl[C3*CC];
__device__ __align__(16) __half g_Wm1h[HID*CC], g_Wm1l[HID*CC];
__device__ __align__(16) __half g_Wph[CC*CC],  g_Wpl[CC*CC];
__device__ __align__(16) __half g_Wfh[FF*CC],  g_Wfl[FF*CC];
__device__ __align__(16) __half g_Wch[CC*FF],  g_Wcl[CC*FF];

// ---------------- helpers ---------------------------------------------------------
__device__ __forceinline__ void wsplit2(float v, __half& h, __half& l) {
    float vs = v * WSCALE;
    h = __float2half(vs);
    l = __float2half(vs - __half2float(h));
}

// activations: plain fp32 -> fp16 convert
__global__ __launch_bounds__(256) void conv_h_kernel(
    const float* __restrict__ src, __half* __restrict__ dst, int n2)
{
    int i = blockIdx.x * 256 + threadIdx.x;
    if (i >= n2) return;
    float2 v = ((const float2*)src)[i];
    __half2 h; h.x = __float2half(v.x); h.y = __float2half(v.y);
    ((__half2*)dst)[i] = h;
}

// weights: scaled hi/lo split
__global__ __launch_bounds__(256) void split_w_kernel(
    const float* __restrict__ src, __half* __restrict__ hi,
    __half* __restrict__ lo, int n2)
{
    int i = blockIdx.x * 256 + threadIdx.x;
    if (i >= n2) return;
    float2 v = ((const float2*)src)[i];
    __half2 h, l;
    wsplit2(v.x, h.x, l.x);
    wsplit2(v.y, h.y, l.y);
    ((__half2*)hi)[i] = h;
    ((__half2*)lo)[i] = l;
}

// fused scaled split of Wq|Wk|Wv into concatenated hi/lo [3C, C]
__global__ __launch_bounds__(256) void split_qkv_kernel(
    const float* __restrict__ Wq, const float* __restrict__ Wk,
    const float* __restrict__ Wv, __half* __restrict__ hi,
    __half* __restrict__ lo)
{
    const int seg = CC * CC / 2;
    int i = blockIdx.x * 256 + threadIdx.x;
    if (i >= 3 * seg) return;
    const float* src = (i < seg) ? Wq : (i < 2 * seg ? Wk : Wv);
    int j = (i < seg) ? i : (i < 2 * seg ? i - seg : i - 2 * seg);
    float2 v = ((const float2*)src)[j];
    __half2 h, l;
    wsplit2(v.x, h.x, l.x);
    wsplit2(v.y, h.y, l.y);
    ((__half2*)hi)[i] = h;
    ((__half2*)lo)[i] = l;
}

// fused scaled split of Wproj, Wfc, Wcp
__global__ __launch_bounds__(256) void split_w3_kernel(
    const float* __restrict__ Wp, const float* __restrict__ Wf,
    const float* __restrict__ Wc,
    __half* __restrict__ Wph, __half* __restrict__ Wpl,
    __half* __restrict__ Wfh, __half* __restrict__ Wfl,
    __half* __restrict__ Wch, __half* __restrict__ Wcl)
{
    const int s1 = CC * CC / 2;
    const int s2 = FF * CC / 2;
    const int s3 = CC * FF / 2;
    int i = blockIdx.x * 256 + threadIdx.x;
    if (i >= s1 + s2 + s3) return;
    const float* src; __half *dh, *dl; int j;
    if (i < s1)           { src = Wp; dh = Wph; dl = Wpl; j = i; }
    else if (i < s1 + s2) { src = Wf; dh = Wfh; dl = Wfl; j = i - s1; }
    else                  { src = Wc; dh = Wch; dl = Wcl; j = i - s1 - s2; }
    float2 v = ((const float2*)src)[j];
    __half2 h, l;
    wsplit2(v.x, h.x, l.x);
    wsplit2(v.y, h.y, l.y);
    ((__half2*)dh)[j] = h;
    ((__half2*)dl)[j] = l;
}

__device__ __forceinline__ void cp16(void* dst, const void* src) {
    unsigned int d = (unsigned int)__cvta_generic_to_shared(dst);
    asm volatile("cp.async.cg.shared.global [%0], [%1], 16;" :: "r"(d), "l"(src));
}
__device__ __forceinline__ void cp4(void* dst, const void* src) {
    unsigned int d = (unsigned int)__cvta_generic_to_shared(dst);
    asm volatile("cp.async.ca.shared.global [%0], [%1], 4;" :: "r"(d), "l"(src));
}

__device__ __forceinline__ void mma16(float c[4], const uint32_t a[4],
                                      uint32_t b0, uint32_t b1) {
    asm volatile(
        "mma.sync.aligned.m16n8k16.row.col.f32.f16.f16.f32 "
        "{%0,%1,%2,%3},{%4,%5,%6,%7},{%8,%9},{%0,%1,%2,%3};"
        : "+f"(c[0]), "+f"(c[1]), "+f"(c[2]), "+f"(c[3])
        : "r"(a[0]), "r"(a[1]), "r"(a[2]), "r"(a[3]), "r"(b0), "r"(b1));
}

#define LDSM4(r, addr) \
    asm volatile("ldmatrix.sync.aligned.m8n8.x4.shared.b16 {%0,%1,%2,%3},[%4];" \
        : "=r"((r)[0]), "=r"((r)[1]), "=r"((r)[2]), "=r"((r)[3]) : "r"(addr))

// ---------------- fp16x2 tensor-core GEMM: out = epi( (A @ (S*W)^T)/S ) -----------
// A fp16 (hi only). W split hi/lo fp16, pre-scaled by WSCALE.
// Terms: a*w_hi + a*w_lo. Epilogue scales by INV_WSCALE.
// EPI: 0 plain, 1 relu(acc+bias), 2 relu(acc)^2, 3 acc+R   OSPLIT: 0 fp32, 1 fp16
#define BM   128
#define BNW  128
#define BKH  32                // k elements per stage
#define STR  40                // padded smem row stride (halfs); conflict-free LDSM
#define STAGE_H (BM*STR)       // halfs per array per stage
#define SMEM_BYTES (2*3*STAGE_H*2)   // 2 stages x 3 arrays = 61440 B

template<int EPI, int OSPLIT>
__global__ __launch_bounds__(256, 2) void hgemm(
    const __half* __restrict__ Ah, const __half* __restrict__ Whg,
    const __half* __restrict__ Wlg,
    const float* __restrict__ bias, const float* __restrict__ R,
    float* __restrict__ out, __half* __restrict__ outh, int M, int N, int K)
{
    extern __shared__ __half sm[];
    const int tid  = threadIdx.x;
    const int lane = tid & 31;
    const int w    = tid >> 5;
    const int g    = lane >> 2;
    const int tig  = lane & 3;
    const int wm   = w & 3;          // 4 warps along M (32 rows)
    const int wn   = w >> 2;         // 2 warps along N (64 cols)
    const int bm0  = blockIdx.y * BM;
    const int bn0  = blockIdx.x * BNW;

    const uint32_t smb = (uint32_t)__cvta_generic_to_shared(sm);
    const uint32_t lofs = (uint32_t)(((lane & 7) + ((lane >> 3) & 1) * 8) * STR
                                     + (lane >> 4) * 8);

    float acc[2][8][4];
#pragma unroll
    for (int i = 0; i < 2; i++)
#pragma unroll
        for (int j = 0; j < 8; j++)
#pragma unroll
            for (int r = 0; r < 4; r++) acc[i][j][r] = 0.f;

    const int NK = K / BKH;

    auto load_stage = [&](int s, int k0) {
        __half* base = sm + s * 3 * STAGE_H;
#pragma unroll
        for (int t = 0; t < 2; t++) {
            int tsk = tid + t * 256;
            int row = tsk >> 2;
            int ch  = (tsk & 3) * 8;
            int so  = row * STR + ch;
            cp16(base + 0 * STAGE_H + so, Ah  + (size_t)(bm0 + row) * K + k0 + ch);
            cp16(base + 1 * STAGE_H + so, Whg + (size_t)(bn0 + row) * K + k0 + ch);
            cp16(base + 2 * STAGE_H + so, Wlg + (size_t)(bn0 + row) * K + k0 + ch);
        }
    };

    load_stage(0, 0);
    asm volatile("cp.async.commit_group;");

    for (int it = 0; it < NK; it++) {
        asm volatile("cp.async.wait_group 0;");
        __syncthreads();

        if (it + 1 < NK) {
            load_stage((it + 1) & 1, (it + 1) * BKH);
            asm volatile("cp.async.commit_group;");
        }

        const uint32_t stageB = smb + (uint32_t)((it & 1) * 3 * STAGE_H) * 2;

        auto loadB = [&](int ksv, int jp, uint32_t bh[4], uint32_t bl[4]) {
            uint32_t tb = stageB + 2u * ((uint32_t)(1 * STAGE_H
                          + (wn * 64 + jp * 16) * STR + ksv) + lofs);
            LDSM4(bh, tb);
            LDSM4(bl, tb + 2u * STAGE_H);
        };

#pragma unroll
        for (int ks = 0; ks < BKH; ks += 16) {
            uint32_t ah[2][4];
#pragma unroll
            for (int i = 0; i < 2; i++) {
                uint32_t ta = stageB + 2u * ((uint32_t)((wm * 32 + i * 16) * STR + ks) + lofs);
                LDSM4(ah[i], ta);
            }
            // software-pipelined B fragments (ping-pong, one-jp lookahead)
            uint32_t bhv[2][4], blv[2][4];
            loadB(ks, 0, bhv[0], blv[0]);
#pragma unroll
            for (int jp = 0; jp < 4; jp++) {
                const int cur = jp & 1;
                if (jp < 3) loadB(ks, jp + 1, bhv[cur ^ 1], blv[cur ^ 1]);
#pragma unroll
                for (int sub = 0; sub < 2; sub++) {
                    const int j = jp * 2 + sub;
                    const uint32_t b0h = bhv[cur][sub], b1h = bhv[cur][sub + 2];
                    const uint32_t b0l = blv[cur][sub], b1l = blv[cur][sub + 2];
                    mma16(acc[0][j], ah[0], b0h, b1h);   // a*w_hi (i=0)
                    mma16(acc[1][j], ah[1], b0h, b1h);   // a*w_hi (i=1)
                    mma16(acc[0][j], ah[0], b0l, b1l);   // a*w_lo (i=0)
                    mma16(acc[1][j], ah[1], b0l, b1l);   // a*w_lo (i=1)
                }
            }
        }
    }

    // ---------------- epilogue (un-scale by 1/WSCALE) ----------------
#pragma unroll
    for (int i = 0; i < 2; i++) {
        const int row0 = bm0 + wm * 32 + i * 16 + g;
        const int row1 = row0 + 8;
#pragma unroll
        for (int j = 0; j < 8; j++) {
            const int col = bn0 + wn * 64 + j * 8 + 2 * tig;
            float2 v01 = make_float2(acc[i][j][0] * INV_WSCALE, acc[i][j][1] * INV_WSCALE);
            float2 v23 = make_float2(acc[i][j][2] * INV_WSCALE, acc[i][j][3] * INV_WSCALE);
            if (EPI == 1) {
                float2 bb = *(const float2*)(bias + col);
                v01.x = fmaxf(v01.x + bb.x, 0.f); v01.y = fmaxf(v01.y + bb.y, 0.f);
                v23.x = fmaxf(v23.x + bb.x, 0.f); v23.y = fmaxf(v23.y + bb.y, 0.f);
            } else if (EPI == 2) {
                v01.x = fmaxf(v01.x, 0.f); v01.x *= v01.x;
                v01.y = fmaxf(v01.y, 0.f); v01.y *= v01.y;
                v23.x = fmaxf(v23.x, 0.f); v23.x *= v23.x;
                v23.y = fmaxf(v23.y, 0.f); v23.y *= v23.y;
            } else if (EPI == 3) {
                float2 r0v = *(const float2*)(R + (size_t)row0 * N + col);
                float2 r1v = *(const float2*)(R + (size_t)row1 * N + col);
                v01.x += r0v.x; v01.y += r0v.y;
                v23.x += r1v.x; v23.y += r1v.y;
            }
            if (OSPLIT) {
                __half2 h2;
                h2.x = __float2half(v01.x); h2.y = __float2half(v01.y);
                *(__half2*)(outh + (size_t)row0 * N + col) = h2;
                h2.x = __float2half(v23.x); h2.y = __float2half(v23.y);
                *(__half2*)(outh + (size_t)row1 * N + col) = h2;
            } else {
                *(float2*)(out + (size_t)row0 * N + col) = v01;
                *(float2*)(out + (size_t)row1 * N + col) = v23;
            }
        }
    }
}

// ---------------- meta-net layer 2 + sigmoid --------------------------------------
__global__ __launch_bounds__(256) void meta2_kernel(
    const float* __restrict__ hbuf, const float* __restrict__ Wm2,
    const float* __restrict__ bm2, float* __restrict__ sur)
{
    int idx = blockIdx.x * blockDim.x + threadIdx.x;
    if (idx >= MM * HH) return;
    int m = idx / HH, h = idx % HH;
    const float* hv = hbuf + (size_t)m * HID;
    const float* w  = Wm2 + (size_t)h * HID;
    float acc = bm2[h];
#pragma unroll 8
    for (int j = 0; j < HID; j++) acc += hv[j] * w[j];
    sur[idx] = 1.f / (1.f + expf(-acc));
}

// ---------------- gated linear-attention scan (fused qkv input) -------------------
#define NSTG 4
#define SUBT 4
#define SSTEP 164

__global__ __launch_bounds__(256) void scan_kernel(
    const float* __restrict__ qkv, const float* __restrict__ sur,
    __half* __restrict__ ysh)
{
    __shared__ float ring[NSTG][SUBT][SSTEP];

    const int bid = blockIdx.x;
    const int b  = bid / (HH * 2);
    const int rem = bid % (HH * 2);
    const int h  = rem >> 1;
    const int eh = rem & 1;
    const int tid = threadIdx.x;
    const int dg  = tid & 7;
    const int el  = tid >> 3;
    const int e   = eh * 32 + el;
    const int d0  = dg * 8;

    const size_t baseIn  = (size_t)b * TT * C3 + (size_t)h * DD;
    const size_t baseOut = (size_t)b * TT * CC + (size_t)h * DD;
    const size_t surBase = (size_t)b * TT * HH + h;

    float s[8];
#pragma unroll
    for (int i = 0; i < 8; i++) s[i] = 0.f;

    auto fill = [&](int stg, int t0) {
        if (tid < 160) {
            int st = tid / 40, c = tid % 40;
            int t = t0 + st;
            if (t < TT) {
                size_t off = baseIn + (size_t)t * C3;
                if (c < 16)
                    cp16(&ring[stg][st][c * 4], qkv + off + CC + c * 4);
                else if (c < 32)
                    cp16(&ring[stg][st][64 + (c - 16) * 4], qkv + off + (c - 16) * 4);
                else
                    cp16(&ring[stg][st][128 + (c - 32) * 4],
                         qkv + off + 2 * CC + eh * 32 + (c - 32) * 4);
            }
        } else if (tid < 164) {
            int st = tid - 160;
            int t = t0 + st;
            if (t < TT)
                cp4(&ring[stg][st][160], sur + surBase + (size_t)t * HH);
        }
    };

#pragma unroll
    for (int i = 0; i < NSTG; i++) {
        fill(i, i * SUBT);
        asm volatile("cp.async.commit_group;");
    }

    const int NB = TT / SUBT;
    for (int ib = 0; ib < NB; ib++) {
        asm volatile("cp.async.wait_group %0;" :: "n"(NSTG - 1));
        __syncthreads();
        const int stg = ib & (NSTG - 1);

#pragma unroll
        for (int st = 0; st < SUBT; st++) {
            const float* row = ring[stg][st];
            const float gt = row[160];
            const float ve = row[128 + el];
            const float dt = 1.f - gt;
            const float c  = gt * ve;
            float accum = 0.f;
#pragma unroll
            for (int i = 0; i < 8; i++) {
                float kv = row[d0 + i];
                float qv = row[64 + d0 + i];
                s[i] = s[i] * dt + c * kv;
                accum = fmaf(qv, s[i], accum);
            }
            accum += __shfl_xor_sync(0xFFFFFFFF, accum, 1);
            accum += __shfl_xor_sync(0xFFFFFFFF, accum, 2);
            accum += __shfl_xor_sync(0xFFFFFFFF, accum, 4);
            if (dg == 0) {
                const int t = ib * SUBT + st;
                ysh[baseOut + (size_t)t * CC + e] = __float2half(accum);
            }
        }
        __syncthreads();
        fill(stg, (ib + NSTG) * SUBT);
        asm volatile("cp.async.commit_group;");
    }
}

// ---------------- RMSNorm -> fp16 -------------------------------------------------
__global__ __launch_bounds__(256) void rmsnorm_kernel(
    const float* __restrict__ y, __half* __restrict__ ynh)
{
    const int row = blockIdx.x;
    const float* p = y + (size_t)row * CC;
    float ss = 0.f;
    for (int i = threadIdx.x; i < CC; i += 256) { float u = p[i]; ss += u * u; }

    __shared__ float red[8];
    for (int o = 16; o > 0; o >>= 1) ss += __shfl_xor_sync(0xFFFFFFFF, ss, o);
    if ((threadIdx.x & 31) == 0) red[threadIdx.x >> 5] = ss;
    __syncthreads();
    if (threadIdx.x < 8) {
        ss = red[threadIdx.x];
        for (int o = 4; o > 0; o >>= 1) ss += __shfl_xor_sync(0xFF, ss, o);
        if (threadIdx.x == 0) red[0] = ss;
    }
    __syncthreads();
    const float inv = rsqrtf(red[0] * (1.f / CC) + 1.1920928955078125e-07f);
    for (int i = threadIdx.x; i < CC; i += 256)
        ynh[(size_t)row * CC + i] = __float2half(p[i] * inv);
}

// ---------------- host driver -----------------------------------------------------
#define SYM(p, s) cudaGetSymbolAddress((void**)&p, s)

extern "C" void kernel_launch(void* const* d_in, const int* in_sizes, int n_in,
                              void* d_out, int out_size)
{
    const float* x     = (const float*)d_in[0];
    const float* Wq    = (const float*)d_in[1];
    const float* Wk    = (const float*)d_in[2];
    const float* Wv    = (const float*)d_in[3];
    const float* Wm1   = (const float*)d_in[4];
    const float* bm1   = (const float*)d_in[5];
    const float* Wm2   = (const float*)d_in[6];
    const float* bm2   = (const float*)d_in[7];
    const float* Wproj = (const float*)d_in[8];
    const float* Wfc   = (const float*)d_in[9];
    const float* Wcp   = (const float*)d_in[10];
    float* out = (float*)d_out;

    float *pqkv, *ph, *psur, *py;
    __half *pxh, *pysh, *pynh, *pffh;
    __half *pWqkvh, *pWqkvl, *pWm1h, *pWm1l;
    __half *pWph, *pWpl, *pWfh, *pWfl, *pWch, *pWcl;

    SYM(pqkv, g_qkv); SYM(ph, g_h); SYM(psur, g_sur); SYM(py, g_y);
    SYM(pxh, g_xh); SYM(pysh, g_ysh); SYM(pynh, g_ynh); SYM(pffh, g_ffh);
    SYM(pWqkvh, g_Wqkvh); SYM(pWqkvl, g_Wqkvl);
    SYM(pWm1h, g_Wm1h); SYM(pWm1l, g_Wm1l);
    SYM(pWph, g_Wph); SYM(pWpl, g_Wpl);
    SYM(pWfh, g_Wfh); SYM(pWfl, g_Wfl);
    SYM(pWch, g_Wch); SYM(pWcl, g_Wcl);

    cudaFuncSetAttribute(hgemm<0,0>, cudaFuncAttributeMaxDynamicSharedMemorySize, SMEM_BYTES);
    cudaFuncSetAttribute(hgemm<1,0>, cudaFuncAttributeMaxDynamicSharedMemorySize, SMEM_BYTES);
    cudaFuncSetAttribute(hgemm<2,1>, cudaFuncAttributeMaxDynamicSharedMemorySize, SMEM_BYTES);
    cudaFuncSetAttribute(hgemm<3,0>, cudaFuncAttributeMaxDynamicSharedMemorySize, SMEM_BYTES);

    dim3 thr(256);
    dim3 gQKV(C3  / BNW, MM / BM);   // 24 x 32 = 768 CTAs
    dim3 gC  (CC  / BNW, MM / BM);
    dim3 gH  (HID / BNW, MM / BM);
    dim3 gFF (FF  / BNW, MM / BM);

    // 0: x -> fp16
    conv_h_kernel<<<(MM * CC / 2 + 255) / 256, thr>>>(x, pxh, MM * CC / 2);
    // 1: fused QKV weight split (scaled)
    split_qkv_kernel<<<(3 * CC * CC / 2 + 255) / 256, thr>>>(Wq, Wk, Wv, pWqkvh, pWqkvl);
    // 2: Wm1 split (scaled)
    split_w_kernel<<<(HID * CC / 2 + 255) / 256, thr>>>(Wm1, pWm1h, pWm1l, HID * CC / 2);

    // 3: fused QKV projection -> qkv fp32
    hgemm<0,0><<<gQKV, thr, SMEM_BYTES>>>(pxh, pWqkvh, pWqkvl, nullptr, nullptr,
                                          pqkv, nullptr, MM, C3, CC);

    // 4: meta net layer 1
    hgemm<1,0><<<gH, thr, SMEM_BYTES>>>(pxh, pWm1h, pWm1l, bm1, nullptr,
                                        ph, nullptr, MM, HID, CC);
    // 5: meta net layer 2 + sigmoid
    meta2_kernel<<<(MM * HH + 255) / 256, thr>>>(ph, Wm2, bm2, psur);

    // 6: gated linear-attention scan -> ys (fp16)
    scan_kernel<<<BB * HH * 2, 256>>>(pqkv, psur, pysh);

    // 7: fused remaining weight splits (scaled)
    {
        int tot = CC * CC / 2 + FF * CC / 2 + CC * FF / 2;
        split_w3_kernel<<<(tot + 255) / 256, thr>>>(Wproj, Wfc, Wcp,
                                                    pWph, pWpl, pWfh, pWfl, pWch, pWcl);
    }

    // 8: output projection (fp32 y, needed for residual)
    hgemm<0,0><<<gC, thr, SMEM_BYTES>>>(pysh, pWph, pWpl, nullptr, nullptr,
                                        py, nullptr, MM, CC, CC);

    // 9: RMSNorm -> yn (fp16)
    rmsnorm_kernel<<<MM, thr>>>(py, pynh);

    // 10: MLP up: ff = relu(yn Wfc^T)^2 (fp16)
    hgemm<2,1><<<gFF, thr, SMEM_BYTES>>>(pynh, pWfh, pWfl, nullptr, nullptr,
                                         nullptr, pffh, MM, FF, CC);
    // 11: MLP down + residual: out = y + ff Wcp^T
    hgemm<3,0><<<gC, thr, SMEM_BYTES>>>(pffh, pWch, pWcl, nullptr, py,
                                        out, nullptr, MM, CC, FF);
}

// round 15
// speedup vs baseline: 1.6010x; 1.1873x over previous
#include <cuda_runtime.h>
#include <cuda_fp16.h>
#include <stdint.h>
#include <math.h>

// Problem dims (fixed)
#define BB   2
#define TT   2048
#define CC   1024
#define HH   16
#define DD   64
#define HID  256
#define FF   4096
#define MM   (BB*TT)   // 4096 rows
#define C3   (3*CC)    // fused qkv width

#define WSCALE   32.0f
#define INV_WSCALE (1.0f/32.0f)

// ---------------- scratch (device globals; no allocation allowed) ----------------
__device__ __align__(16) float g_qkv[MM*C3];     // fused q|k|v fp32
__device__ __align__(16) float g_h [MM*HID];
__device__ __align__(16) float g_sur[MM*HH];
__device__ __align__(16) float g_y [MM*CC];
// fp16 activations
__device__ __align__(16) __half g_xh [MM*CC];
__device__ __align__(16) __half g_ysh[MM*CC];
__device__ __align__(16) __half g_ynh[MM*CC];
__device__ __align__(16) __half g_ffh[MM*FF];
// fp16 weights: 2-term (scaled hi/lo) for qkv/meta/proj, 1-term for fc/cp
__device__ __align__(16) __half g_Wqkvh[C3*CC], g_Wqkvl[C3*CC];
__device__ __align__(16) __half g_Wm1h[HID*CC], g_Wm1l[HID*CC];
__device__ __align__(16) __half g_Wph[CC*CC],  g_Wpl[CC*CC];
__device__ __align__(16) __half g_Wfh[FF*CC];
__device__ __align__(16) __half g_Wch[CC*FF];

// ---------------- helpers ---------------------------------------------------------
__device__ __forceinline__ void wsplit2(float v, __half& h, __half& l) {
    float vs = v * WSCALE;
    h = __float2half(vs);
    l = __float2half(vs - __half2float(h));
}

// plain fp32 -> fp16 convert
__global__ __launch_bounds__(256) void conv_h_kernel(
    const float* __restrict__ src, __half* __restrict__ dst, int n2)
{
    int i = blockIdx.x * 256 + threadIdx.x;
    if (i >= n2) return;
    float2 v = ((const float2*)src)[i];
    __half2 h; h.x = __float2half(v.x); h.y = __float2half(v.y);
    ((__half2*)dst)[i] = h;
}

// scaled hi/lo split
__global__ __launch_bounds__(256) void split_w_kernel(
    const float* __restrict__ src, __half* __restrict__ hi,
    __half* __restrict__ lo, int n2)
{
    int i = blockIdx.x * 256 + threadIdx.x;
    if (i >= n2) return;
    float2 v = ((const float2*)src)[i];
    __half2 h, l;
    wsplit2(v.x, h.x, l.x);
    wsplit2(v.y, h.y, l.y);
    ((__half2*)hi)[i] = h;
    ((__half2*)lo)[i] = l;
}

// fused scaled split of Wq|Wk|Wv into concatenated hi/lo [3C, C]
__global__ __launch_bounds__(256) void split_qkv_kernel(
    const float* __restrict__ Wq, const float* __restrict__ Wk,
    const float* __restrict__ Wv, __half* __restrict__ hi,
    __half* __restrict__ lo)
{
    const int seg = CC * CC / 2;
    int i = blockIdx.x * 256 + threadIdx.x;
    if (i >= 3 * seg) return;
    const float* src = (i < seg) ? Wq : (i < 2 * seg ? Wk : Wv);
    int j = (i < seg) ? i : (i < 2 * seg ? i - seg : i - 2 * seg);
    float2 v = ((const float2*)src)[j];
    __half2 h, l;
    wsplit2(v.x, h.x, l.x);
    wsplit2(v.y, h.y, l.y);
    ((__half2*)hi)[i] = h;
    ((__half2*)lo)[i] = l;
}

// fused weight prep: Wproj (2-term scaled), Wfc (1-term), Wcp (1-term)
__global__ __launch_bounds__(256) void prep_w3_kernel(
    const float* __restrict__ Wp, const float* __restrict__ Wf,
    const float* __restrict__ Wc,
    __half* __restrict__ Wph, __half* __restrict__ Wpl,
    __half* __restrict__ Wfh, __half* __restrict__ Wch)
{
    const int s1 = CC * CC / 2;
    const int s2 = FF * CC / 2;
    const int s3 = CC * FF / 2;
    int i = blockIdx.x * 256 + threadIdx.x;
    if (i >= s1 + s2 + s3) return;
    if (i < s1) {
        float2 v = ((const float2*)Wp)[i];
        __half2 h, l;
        wsplit2(v.x, h.x, l.x);
        wsplit2(v.y, h.y, l.y);
        ((__half2*)Wph)[i] = h;
        ((__half2*)Wpl)[i] = l;
    } else if (i < s1 + s2) {
        int j = i - s1;
        float2 v = ((const float2*)Wf)[j];
        __half2 h; h.x = __float2half(v.x); h.y = __float2half(v.y);
        ((__half2*)Wfh)[j] = h;
    } else {
        int j = i - s1 - s2;
        float2 v = ((const float2*)Wc)[j];
        __half2 h; h.x = __float2half(v.x); h.y = __float2half(v.y);
        ((__half2*)Wch)[j] = h;
    }
}

__device__ __forceinline__ void cp16(void* dst, const void* src) {
    unsigned int d = (unsigned int)__cvta_generic_to_shared(dst);
    asm volatile("cp.async.cg.shared.global [%0], [%1], 16;" :: "r"(d), "l"(src));
}
__device__ __forceinline__ void cp4(void* dst, const void* src) {
    unsigned int d = (unsigned int)__cvta_generic_to_shared(dst);
    asm volatile("cp.async.ca.shared.global [%0], [%1], 4;" :: "r"(d), "l"(src));
}

__device__ __forceinline__ void mma16(float c[4], const uint32_t a[4],
                                      uint32_t b0, uint32_t b1) {
    asm volatile(
        "mma.sync.aligned.m16n8k16.row.col.f32.f16.f16.f32 "
        "{%0,%1,%2,%3},{%4,%5,%6,%7},{%8,%9},{%0,%1,%2,%3};"
        : "+f"(c[0]), "+f"(c[1]), "+f"(c[2]), "+f"(c[3])
        : "r"(a[0]), "r"(a[1]), "r"(a[2]), "r"(a[3]), "r"(b0), "r"(b1));
}

#define LDSM4(r, addr) \
    asm volatile("ldmatrix.sync.aligned.m8n8.x4.shared.b16 {%0,%1,%2,%3},[%4];" \
        : "=r"((r)[0]), "=r"((r)[1]), "=r"((r)[2]), "=r"((r)[3]) : "r"(addr))

// ---------------- fp16 tensor-core GEMM: out = epi( A @ W^T ) ---------------------
// TERMS=2: W pre-scaled hi/lo (x WSCALE), acc un-scaled in epilogue.
// TERMS=1: W plain fp16, no scaling.
// EPI: 0 plain, 1 relu(acc+bias), 2 relu(acc)^2, 3 acc+R   OSPLIT: 0 fp32, 1 fp16
#define BM   128
#define BNW  128
#define BKH  32                // k elements per stage
#define STR  40                // padded smem row stride (halfs); conflict-free LDSM
#define STAGE_H (BM*STR)       // halfs per array per stage
#define SMEM_B2 (2*3*STAGE_H*2)   // 2 stages x 3 arrays = 61440 B
#define SMEM_B1 (2*2*STAGE_H*2)   // 2 stages x 2 arrays = 40960 B

template<int EPI, int OSPLIT, int TERMS>
__global__ __launch_bounds__(256, 2) void hgemm(
    const __half* __restrict__ Ah, const __half* __restrict__ Whg,
    const __half* __restrict__ Wlg,
    const float* __restrict__ bias, const float* __restrict__ R,
    float* __restrict__ out, __half* __restrict__ outh, int M, int N, int K)
{
    extern __shared__ __half sm[];
    const int NARR = (TERMS == 2) ? 3 : 2;
    const int tid  = threadIdx.x;
    const int lane = tid & 31;
    const int w    = tid >> 5;
    const int g    = lane >> 2;
    const int tig  = lane & 3;
    const int wm   = w & 3;          // 4 warps along M (32 rows)
    const int wn   = w >> 2;         // 2 warps along N (64 cols)
    const int bm0  = blockIdx.y * BM;
    const int bn0  = blockIdx.x * BNW;

    const uint32_t smb = (uint32_t)__cvta_generic_to_shared(sm);
    const uint32_t lofs = (uint32_t)(((lane & 7) + ((lane >> 3) & 1) * 8) * STR
                                     + (lane >> 4) * 8);

    float acc[2][8][4];
#pragma unroll
    for (int i = 0; i < 2; i++)
#pragma unroll
        for (int j = 0; j < 8; j++)
#pragma unroll
            for (int r = 0; r < 4; r++) acc[i][j][r] = 0.f;

    const int NK = K / BKH;

    auto load_stage = [&](int s, int k0) {
        __half* base = sm + s * NARR * STAGE_H;
#pragma unroll
        for (int t = 0; t < 2; t++) {
            int tsk = tid + t * 256;
            int row = tsk >> 2;
            int ch  = (tsk & 3) * 8;
            int so  = row * STR + ch;
            cp16(base + 0 * STAGE_H + so, Ah  + (size_t)(bm0 + row) * K + k0 + ch);
            cp16(base + 1 * STAGE_H + so, Whg + (size_t)(bn0 + row) * K + k0 + ch);
            if (TERMS == 2)
                cp16(base + 2 * STAGE_H + so, Wlg + (size_t)(bn0 + row) * K + k0 + ch);
        }
    };

    load_stage(0, 0);
    asm volatile("cp.async.commit_group;");

    for (int it = 0; it < NK; it++) {
        asm volatile("cp.async.wait_group 0;");
        __syncthreads();

        if (it + 1 < NK) {
            load_stage((it + 1) & 1, (it + 1) * BKH);
            asm volatile("cp.async.commit_group;");
        }

        const uint32_t stageB = smb + (uint32_t)((it & 1) * NARR * STAGE_H) * 2;

#pragma unroll
        for (int ks = 0; ks < BKH; ks += 16) {
            uint32_t ah[2][4];
#pragma unroll
            for (int i = 0; i < 2; i++) {
                uint32_t ta = stageB + 2u * ((uint32_t)((wm * 32 + i * 16) * STR + ks) + lofs);
                LDSM4(ah[i], ta);
            }
            // software-pipelined B fragments (ping-pong, one-jp lookahead)
            uint32_t bhv[2][4], blv[2][4];
            {
                uint32_t tb = stageB + 2u * ((uint32_t)(1 * STAGE_H + (wn * 64) * STR + ks) + lofs);
                LDSM4(bhv[0], tb);
                if (TERMS == 2) LDSM4(blv[0], tb + 2u * STAGE_H);
            }
#pragma unroll
            for (int jp = 0; jp < 4; jp++) {
                const int cur = jp & 1;
                if (jp < 3) {
                    uint32_t tb = stageB + 2u * ((uint32_t)(1 * STAGE_H
                                  + (wn * 64 + (jp + 1) * 16) * STR + ks) + lofs);
                    LDSM4(bhv[cur ^ 1], tb);
                    if (TERMS == 2) LDSM4(blv[cur ^ 1], tb + 2u * STAGE_H);
                }
#pragma unroll
                for (int sub = 0; sub < 2; sub++) {
                    const int j = jp * 2 + sub;
                    const uint32_t b0h = bhv[cur][sub], b1h = bhv[cur][sub + 2];
                    mma16(acc[0][j], ah[0], b0h, b1h);
                    mma16(acc[1][j], ah[1], b0h, b1h);
                    if (TERMS == 2) {
                        const uint32_t b0l = blv[cur][sub], b1l = blv[cur][sub + 2];
                        mma16(acc[0][j], ah[0], b0l, b1l);
                        mma16(acc[1][j], ah[1], b0l, b1l);
                    }
                }
            }
        }
    }

    // ---------------- epilogue ----------------
    const float scale = (TERMS == 2) ? INV_WSCALE : 1.0f;
#pragma unroll
    for (int i = 0; i < 2; i++) {
        const int row0 = bm0 + wm * 32 + i * 16 + g;
        const int row1 = row0 + 8;
#pragma unroll
        for (int j = 0; j < 8; j++) {
            const int col = bn0 + wn * 64 + j * 8 + 2 * tig;
            float2 v01 = make_float2(acc[i][j][0] * scale, acc[i][j][1] * scale);
            float2 v23 = make_float2(acc[i][j][2] * scale, acc[i][j][3] * scale);
            if (EPI == 1) {
                float2 bb = *(const float2*)(bias + col);
                v01.x = fmaxf(v01.x + bb.x, 0.f); v01.y = fmaxf(v01.y + bb.y, 0.f);
                v23.x = fmaxf(v23.x + bb.x, 0.f); v23.y = fmaxf(v23.y + bb.y, 0.f);
            } else if (EPI == 2) {
                v01.x = fmaxf(v01.x, 0.f); v01.x *= v01.x;
                v01.y = fmaxf(v01.y, 0.f); v01.y *= v01.y;
                v23.x = fmaxf(v23.x, 0.f); v23.x *= v23.x;
                v23.y = fmaxf(v23.y, 0.f); v23.y *= v23.y;
            } else if (EPI == 3) {
                float2 r0v = *(const float2*)(R + (size_t)row0 * N + col);
                float2 r1v = *(const float2*)(R + (size_t)row1 * N + col);
                v01.x += r0v.x; v01.y += r0v.y;
                v23.x += r1v.x; v23.y += r1v.y;
            }
            if (OSPLIT) {
                __half2 h2;
                h2.x = __float2half(v01.x); h2.y = __float2half(v01.y);
                *(__half2*)(outh + (size_t)row0 * N + col) = h2;
                h2.x = __float2half(v23.x); h2.y = __float2half(v23.y);
                *(__half2*)(outh + (size_t)row1 * N + col) = h2;
            } else {
                *(float2*)(out + (size_t)row0 * N + col) = v01;
                *(float2*)(out + (size_t)row1 * N + col) = v23;
            }
        }
    }
}

// ---------------- meta-net layer 2 + sigmoid --------------------------------------
__global__ __launch_bounds__(256) void meta2_kernel(
    const float* __restrict__ hbuf, const float* __restrict__ Wm2,
    const float* __restrict__ bm2, float* __restrict__ sur)
{
    int idx = blockIdx.x * blockDim.x + threadIdx.x;
    if (idx >= MM * HH) return;
    int m = idx / HH, h = idx % HH;
    const float* hv = hbuf + (size_t)m * HID;
    const float* w  = Wm2 + (size_t)h * HID;
    float acc = bm2[h];
#pragma unroll 8
    for (int j = 0; j < HID; j++) acc += hv[j] * w[j];
    sur[idx] = 1.f / (1.f + expf(-acc));
}

// ---------------- gated linear-attention scan (fused qkv input) -------------------
// 128 CTAs (BB*HH*4), 128 threads. Block owns 16 v-columns; thread (el,dg) owns
// 8 state rows for column e = quarter*16+el. k/q re-reads hit L2.
#define NSTG 4
#define SUBT 4
#define SSTEP 148   // floats: k[64] q[64] v[16] g[1] pad[3]

__global__ __launch_bounds__(128) void scan_kernel(
    const float* __restrict__ qkv, const float* __restrict__ sur,
    __half* __restrict__ ysh)
{
    __shared__ float ring[NSTG][SUBT][SSTEP];

    const int bid = blockIdx.x;
    const int b   = bid / (HH * 4);
    const int rem = bid % (HH * 4);
    const int h   = rem >> 2;
    const int eq  = rem & 3;          // 16-column quarter
    const int tid = threadIdx.x;
    const int dg  = tid & 7;
    const int el  = tid >> 3;         // 0..15
    const int e   = eq * 16 + el;
    const int d0  = dg * 8;

    const size_t baseIn  = (size_t)b * TT * C3 + (size_t)h * DD;
    const size_t baseOut = (size_t)b * TT * CC + (size_t)h * DD;
    const size_t surBase = (size_t)b * TT * HH + h;

    float s[8];
#pragma unroll
    for (int i = 0; i < 8; i++) s[i] = 0.f;

    // producer: 4 subt x 36 16B-chunks + 4 4B g's = 148 tasks over 128 threads
    auto fill = [&](int stg, int t0) {
        for (int idx = tid; idx < 4 * 36 + 4; idx += 128) {
            if (idx < 144) {
                int st = idx / 36, c = idx % 36;
                int t = t0 + st;
                if (t < TT) {
                    size_t off = baseIn + (size_t)t * C3;
                    if (c < 16)        // k
                        cp16(&ring[stg][st][c * 4], qkv + off + CC + c * 4);
                    else if (c < 32)   // q
                        cp16(&ring[stg][st][64 + (c - 16) * 4], qkv + off + (c - 16) * 4);
                    else               // v (this block's 16 columns)
                        cp16(&ring[stg][st][128 + (c - 32) * 4],
                             qkv + off + 2 * CC + eq * 16 + (c - 32) * 4);
                }
            } else {
                int st = idx - 144;
                int t = t0 + st;
                if (t < TT)
                    cp4(&ring[stg][st][144], sur + surBase + (size_t)t * HH);
            }
        }
    };

#pragma unroll
    for (int i = 0; i < NSTG; i++) {
        fill(i, i * SUBT);
        asm volatile("cp.async.commit_group;");
    }

    const int NB = TT / SUBT;
    for (int ib = 0; ib < NB; ib++) {
        asm volatile("cp.async.wait_group %0;" :: "n"(NSTG - 1));
        __syncthreads();
        const int stg = ib & (NSTG - 1);

#pragma unroll
        for (int st = 0; st < SUBT; st++) {
            const float* row = ring[stg][st];
            const float gt = row[144];
            const float ve = row[128 + el];
            const float dt = 1.f - gt;
            const float c  = gt * ve;
            float accum = 0.f;
#pragma unroll
            for (int i = 0; i < 8; i++) {
                float kv = row[d0 + i];
                float qv = row[64 + d0 + i];
                s[i] = s[i] * dt + c * kv;
                accum = fmaf(qv, s[i], accum);
            }
            accum += __shfl_xor_sync(0xFFFFFFFF, accum, 1);
            accum += __shfl_xor_sync(0xFFFFFFFF, accum, 2);
            accum += __shfl_xor_sync(0xFFFFFFFF, accum, 4);
            if (dg == 0) {
                const int t = ib * SUBT + st;
                ysh[baseOut + (size_t)t * CC + e] = __float2half(accum);
            }
        }
        __syncthreads();
        fill(stg, (ib + NSTG) * SUBT);
        asm volatile("cp.async.commit_group;");
    }
}

// ---------------- RMSNorm -> fp16 -------------------------------------------------
__global__ __launch_bounds__(256) void rmsnorm_kernel(
    const float* __restrict__ y, __half* __restrict__ ynh)
{
    const int row = blockIdx.x;
    const float* p = y + (size_t)row * CC;
    float ss = 0.f;
    for (int i = threadIdx.x; i < CC; i += 256) { float u = p[i]; ss += u * u; }

    __shared__ float red[8];
    for (int o = 16; o > 0; o >>= 1) ss += __shfl_xor_sync(0xFFFFFFFF, ss, o);
    if ((threadIdx.x & 31) == 0) red[threadIdx.x >> 5] = ss;
    __syncthreads();
    if (threadIdx.x < 8) {
        ss = red[threadIdx.x];
        for (int o = 4; o > 0; o >>= 1) ss += __shfl_xor_sync(0xFF, ss, o);
        if (threadIdx.x == 0) red[0] = ss;
    }
    __syncthreads();
    const float inv = rsqrtf(red[0] * (1.f / CC) + 1.1920928955078125e-07f);
    for (int i = threadIdx.x; i < CC; i += 256)
        ynh[(size_t)row * CC + i] = __float2half(p[i] * inv);
}

// ---------------- host driver -----------------------------------------------------
#define SYM(p, s) cudaGetSymbolAddress((void**)&p, s)

extern "C" void kernel_launch(void* const* d_in, const int* in_sizes, int n_in,
                              void* d_out, int out_size)
{
    const float* x     = (const float*)d_in[0];
    const float* Wq    = (const float*)d_in[1];
    const float* Wk    = (const float*)d_in[2];
    const float* Wv    = (const float*)d_in[3];
    const float* Wm1   = (const float*)d_in[4];
    const float* bm1   = (const float*)d_in[5];
    const float* Wm2   = (const float*)d_in[6];
    const float* bm2   = (const float*)d_in[7];
    const float* Wproj = (const float*)d_in[8];
    const float* Wfc   = (const float*)d_in[9];
    const float* Wcp   = (const float*)d_in[10];
    float* out = (float*)d_out;

    float *pqkv, *ph, *psur, *py;
    __half *pxh, *pysh, *pynh, *pffh;
    __half *pWqkvh, *pWqkvl, *pWm1h, *pWm1l;
    __half *pWph, *pWpl, *pWfh, *pWch;

    SYM(pqkv, g_qkv); SYM(ph, g_h); SYM(psur, g_sur); SYM(py, g_y);
    SYM(pxh, g_xh); SYM(pysh, g_ysh); SYM(pynh, g_ynh); SYM(pffh, g_ffh);
    SYM(pWqkvh, g_Wqkvh); SYM(pWqkvl, g_Wqkvl);
    SYM(pWm1h, g_Wm1h); SYM(pWm1l, g_Wm1l);
    SYM(pWph, g_Wph); SYM(pWpl, g_Wpl);
    SYM(pWfh, g_Wfh); SYM(pWch, g_Wch);

    cudaFuncSetAttribute(hgemm<0,0,2>, cudaFuncAttributeMaxDynamicSharedMemorySize, SMEM_B2);
    cudaFuncSetAttribute(hgemm<1,0,2>, cudaFuncAttributeMaxDynamicSharedMemorySize, SMEM_B2);
    cudaFuncSetAttribute(hgemm<2,1,1>, cudaFuncAttributeMaxDynamicSharedMemorySize, SMEM_B1);
    cudaFuncSetAttribute(hgemm<3,0,1>, cudaFuncAttributeMaxDynamicSharedMemorySize, SMEM_B1);

    dim3 thr(256);
    dim3 gQKV(C3  / BNW, MM / BM);   // 24 x 32 = 768 CTAs
    dim3 gC  (CC  / BNW, MM / BM);
    dim3 gH  (HID / BNW, MM / BM);
    dim3 gFF (FF  / BNW, MM / BM);

    // 0: x -> fp16
    conv_h_kernel<<<(MM * CC / 2 + 255) / 256, thr>>>(x, pxh, MM * CC / 2);
    // 1: fused QKV weight split (scaled, 2-term)
    split_qkv_kernel<<<(3 * CC * CC / 2 + 255) / 256, thr>>>(Wq, Wk, Wv, pWqkvh, pWqkvl);
    // 2: Wm1 split (scaled, 2-term)
    split_w_kernel<<<(HID * CC / 2 + 255) / 256, thr>>>(Wm1, pWm1h, pWm1l, HID * CC / 2);

    // 3: fused QKV projection -> qkv fp32 (2-term)
    hgemm<0,0,2><<<gQKV, thr, SMEM_B2>>>(pxh, pWqkvh, pWqkvl, nullptr, nullptr,
                                         pqkv, nullptr, MM, C3, CC);

    // 4: meta net layer 1 (2-term)
    hgemm<1,0,2><<<gH, thr, SMEM_B2>>>(pxh, pWm1h, pWm1l, bm1, nullptr,
                                       ph, nullptr, MM, HID, CC);
    // 5: meta net layer 2 + sigmoid
    meta2_kernel<<<(MM * HH + 255) / 256, thr>>>(ph, Wm2, bm2, psur);

    // 6: gated linear-attention scan -> ys (fp16)
    scan_kernel<<<BB * HH * 4, 128>>>(pqkv, psur, pysh);

    // 7: fused remaining weight prep (Wproj 2-term; Wfc/Wcp 1-term)
    {
        int tot = CC * CC / 2 + FF * CC / 2 + CC * FF / 2;
        prep_w3_kernel<<<(tot + 255) / 256, thr>>>(Wproj, Wfc, Wcp,
                                                   pWph, pWpl, pWfh, pWch);
    }

    // 8: output projection (fp32 y, needed for residual; 2-term)
    hgemm<0,0,2><<<gC, thr, SMEM_B2>>>(pysh, pWph, pWpl, nullptr, nullptr,
                                       py, nullptr, MM, CC, CC);

    // 9: RMSNorm -> yn (fp16)
    rmsnorm_kernel<<<MM, thr>>>(py, pynh);

    // 10: MLP up: ff = relu(yn Wfc^T)^2 (fp16; 1-term)
    hgemm<2,1,1><<<gFF, thr, SMEM_B1>>>(pynh, pWfh, nullptr, nullptr, nullptr,
                                        nullptr, pffh, MM, FF, CC);
    // 11: MLP down + residual: out = y + ff Wcp^T (1-term)
    hgemm<3,0,1><<<gC, thr, SMEM_B1>>>(pffh, pWch, nullptr, nullptr, py,
                                       out, nullptr, MM, CC, FF);
}

// round 16
// speedup vs baseline: 1.7795x; 1.1115x over previous
#include <cuda_runtime.h>
#include <cuda_fp16.h>
#include <stdint.h>
#include <math.h>

// Problem dims (fixed)
#define BB   2
#define TT   2048
#define CC   1024
#define HH   16
#define DD   64
#define HID  256
#define FF   4096
#define MM   (BB*TT)   // 4096 rows
#define C3   (3*CC)    // fused qkv width

#define WSCALE   32.0f
#define INV_WSCALE (1.0f/32.0f)

// ---------------- scratch (device globals; no allocation allowed) ----------------
__device__ __align__(16) float g_qkv[MM*C3];     // fused q|k|v fp32
__device__ __align__(16) float g_h [MM*HID];
__device__ __align__(16) float g_sur[MM*HH];
__device__ __align__(16) float g_y [MM*CC];
// fp16 activations
__device__ __align__(16) __half g_xh [MM*CC];
__device__ __align__(16) __half g_ysh[MM*CC];
__device__ __align__(16) __half g_ynh[MM*CC];
__device__ __align__(16) __half g_ffh[MM*FF];
// fp16 weights: 1-term for qkv/proj/fc/cp; 2-term (scaled hi/lo) for meta1 only
__device__ __align__(16) __half g_Wqkvh[C3*CC];
__device__ __align__(16) __half g_Wm1h[HID*CC], g_Wm1l[HID*CC];
__device__ __align__(16) __half g_Wph[CC*CC];
__device__ __align__(16) __half g_Wfh[FF*CC];
__device__ __align__(16) __half g_Wch[CC*FF];

// ---------------- helpers ---------------------------------------------------------
__device__ __forceinline__ void wsplit2(float v, __half& h, __half& l) {
    float vs = v * WSCALE;
    h = __float2half(vs);
    l = __float2half(vs - __half2float(h));
}

// plain fp32 -> fp16 convert
__global__ __launch_bounds__(256) void conv_h_kernel(
    const float* __restrict__ src, __half* __restrict__ dst, int n2)
{
    int i = blockIdx.x * 256 + threadIdx.x;
    if (i >= n2) return;
    float2 v = ((const float2*)src)[i];
    __half2 h; h.x = __float2half(v.x); h.y = __float2half(v.y);
    ((__half2*)dst)[i] = h;
}

// scaled hi/lo split (meta1 weights only)
__global__ __launch_bounds__(256) void split_w_kernel(
    const float* __restrict__ src, __half* __restrict__ hi,
    __half* __restrict__ lo, int n2)
{
    int i = blockIdx.x * 256 + threadIdx.x;
    if (i >= n2) return;
    float2 v = ((const float2*)src)[i];
    __half2 h, l;
    wsplit2(v.x, h.x, l.x);
    wsplit2(v.y, h.y, l.y);
    ((__half2*)hi)[i] = h;
    ((__half2*)lo)[i] = l;
}

// fused fp16 convert of Wq|Wk|Wv into concatenated [3C, C]
__global__ __launch_bounds__(256) void conv_qkv_kernel(
    const float* __restrict__ Wq, const float* __restrict__ Wk,
    const float* __restrict__ Wv, __half* __restrict__ dst)
{
    const int seg = CC * CC / 2;
    int i = blockIdx.x * 256 + threadIdx.x;
    if (i >= 3 * seg) return;
    const float* src = (i < seg) ? Wq : (i < 2 * seg ? Wk : Wv);
    int j = (i < seg) ? i : (i < 2 * seg ? i - seg : i - 2 * seg);
    float2 v = ((const float2*)src)[j];
    __half2 h; h.x = __float2half(v.x); h.y = __float2half(v.y);
    ((__half2*)dst)[i] = h;
}

// fused fp16 convert of Wproj, Wfc, Wcp (all 1-term)
__global__ __launch_bounds__(256) void conv_w3_kernel(
    const float* __restrict__ Wp, const float* __restrict__ Wf,
    const float* __restrict__ Wc,
    __half* __restrict__ Wph, __half* __restrict__ Wfh, __half* __restrict__ Wch)
{
    const int s1 = CC * CC / 2;
    const int s2 = FF * CC / 2;
    const int s3 = CC * FF / 2;
    int i = blockIdx.x * 256 + threadIdx.x;
    if (i >= s1 + s2 + s3) return;
    const float* src; __half* dst; int j;
    if (i < s1)           { src = Wp; dst = Wph; j = i; }
    else if (i < s1 + s2) { src = Wf; dst = Wfh; j = i - s1; }
    else                  { src = Wc; dst = Wch; j = i - s1 - s2; }
    float2 v = ((const float2*)src)[j];
    __half2 h; h.x = __float2half(v.x); h.y = __float2half(v.y);
    ((__half2*)dst)[j] = h;
}

__device__ __forceinline__ void cp16(void* dst, const void* src) {
    unsigned int d = (unsigned int)__cvta_generic_to_shared(dst);
    asm volatile("cp.async.cg.shared.global [%0], [%1], 16;" :: "r"(d), "l"(src));
}
__device__ __forceinline__ void cp4(void* dst, const void* src) {
    unsigned int d = (unsigned int)__cvta_generic_to_shared(dst);
    asm volatile("cp.async.ca.shared.global [%0], [%1], 4;" :: "r"(d), "l"(src));
}

__device__ __forceinline__ void mma16(float c[4], const uint32_t a[4],
                                      uint32_t b0, uint32_t b1) {
    asm volatile(
        "mma.sync.aligned.m16n8k16.row.col.f32.f16.f16.f32 "
        "{%0,%1,%2,%3},{%4,%5,%6,%7},{%8,%9},{%0,%1,%2,%3};"
        : "+f"(c[0]), "+f"(c[1]), "+f"(c[2]), "+f"(c[3])
        : "r"(a[0]), "r"(a[1]), "r"(a[2]), "r"(a[3]), "r"(b0), "r"(b1));
}

#define LDSM4(r, addr) \
    asm volatile("ldmatrix.sync.aligned.m8n8.x4.shared.b16 {%0,%1,%2,%3},[%4];" \
        : "=r"((r)[0]), "=r"((r)[1]), "=r"((r)[2]), "=r"((r)[3]) : "r"(addr))

// ---------------- fp16 tensor-core GEMM: out = epi( A @ W^T ) ---------------------
// TERMS=2: W pre-scaled hi/lo (x WSCALE), acc un-scaled in epilogue.
// TERMS=1: W plain fp16, no scaling.
// EPI: 0 plain, 1 relu(acc+bias), 2 relu(acc)^2, 3 acc+R   OSPLIT: 0 fp32, 1 fp16
#define BM   128
#define BNW  128
#define BKH  32                // k elements per stage
#define STR  40                // padded smem row stride (halfs); conflict-free LDSM
#define STAGE_H (BM*STR)       // halfs per array per stage
#define SMEM_B2 (2*3*STAGE_H*2)   // 61440 B
#define SMEM_B1 (2*2*STAGE_H*2)   // 40960 B

template<int EPI, int OSPLIT, int TERMS>
__global__ __launch_bounds__(256, 2) void hgemm(
    const __half* __restrict__ Ah, const __half* __restrict__ Whg,
    const __half* __restrict__ Wlg,
    const float* __restrict__ bias, const float* __restrict__ R,
    float* __restrict__ out, __half* __restrict__ outh, int M, int N, int K)
{
    extern __shared__ __half sm[];
    const int NARR = (TERMS == 2) ? 3 : 2;
    const int tid  = threadIdx.x;
    const int lane = tid & 31;
    const int w    = tid >> 5;
    const int g    = lane >> 2;
    const int tig  = lane & 3;
    const int wm   = w & 3;          // 4 warps along M (32 rows)
    const int wn   = w >> 2;         // 2 warps along N (64 cols)
    const int bm0  = blockIdx.y * BM;
    const int bn0  = blockIdx.x * BNW;

    const uint32_t smb = (uint32_t)__cvta_generic_to_shared(sm);
    const uint32_t lofs = (uint32_t)(((lane & 7) + ((lane >> 3) & 1) * 8) * STR
                                     + (lane >> 4) * 8);

    float acc[2][8][4];
#pragma unroll
    for (int i = 0; i < 2; i++)
#pragma unroll
        for (int j = 0; j < 8; j++)
#pragma unroll
            for (int r = 0; r < 4; r++) acc[i][j][r] = 0.f;

    const int NK = K / BKH;

    auto load_stage = [&](int s, int k0) {
        __half* base = sm + s * NARR * STAGE_H;
#pragma unroll
        for (int t = 0; t < 2; t++) {
            int tsk = tid + t * 256;
            int row = tsk >> 2;
            int ch  = (tsk & 3) * 8;
            int so  = row * STR + ch;
            cp16(base + 0 * STAGE_H + so, Ah  + (size_t)(bm0 + row) * K + k0 + ch);
            cp16(base + 1 * STAGE_H + so, Whg + (size_t)(bn0 + row) * K + k0 + ch);
            if (TERMS == 2)
                cp16(base + 2 * STAGE_H + so, Wlg + (size_t)(bn0 + row) * K + k0 + ch);
        }
    };

    load_stage(0, 0);
    asm volatile("cp.async.commit_group;");

    for (int it = 0; it < NK; it++) {
        asm volatile("cp.async.wait_group 0;");
        __syncthreads();

        if (it + 1 < NK) {
            load_stage((it + 1) & 1, (it + 1) * BKH);
            asm volatile("cp.async.commit_group;");
        }

        const uint32_t stageB = smb + (uint32_t)((it & 1) * NARR * STAGE_H) * 2;

#pragma unroll
        for (int ks = 0; ks < BKH; ks += 16) {
            uint32_t ah[2][4];
#pragma unroll
            for (int i = 0; i < 2; i++) {
                uint32_t ta = stageB + 2u * ((uint32_t)((wm * 32 + i * 16) * STR + ks) + lofs);
                LDSM4(ah[i], ta);
            }
            // software-pipelined B fragments (ping-pong, one-jp lookahead)
            uint32_t bhv[2][4], blv[2][4];
            {
                uint32_t tb = stageB + 2u * ((uint32_t)(1 * STAGE_H + (wn * 64) * STR + ks) + lofs);
                LDSM4(bhv[0], tb);
                if (TERMS == 2) LDSM4(blv[0], tb + 2u * STAGE_H);
            }
#pragma unroll
            for (int jp = 0; jp < 4; jp++) {
                const int cur = jp & 1;
                if (jp < 3) {
                    uint32_t tb = stageB + 2u * ((uint32_t)(1 * STAGE_H
                                  + (wn * 64 + (jp + 1) * 16) * STR + ks) + lofs);
                    LDSM4(bhv[cur ^ 1], tb);
                    if (TERMS == 2) LDSM4(blv[cur ^ 1], tb + 2u * STAGE_H);
                }
#pragma unroll
                for (int sub = 0; sub < 2; sub++) {
                    const int j = jp * 2 + sub;
                    const uint32_t b0h = bhv[cur][sub], b1h = bhv[cur][sub + 2];
                    mma16(acc[0][j], ah[0], b0h, b1h);
                    mma16(acc[1][j], ah[1], b0h, b1h);
                    if (TERMS == 2) {
                        const uint32_t b0l = blv[cur][sub], b1l = blv[cur][sub + 2];
                        mma16(acc[0][j], ah[0], b0l, b1l);
                        mma16(acc[1][j], ah[1], b0l, b1l);
                    }
                }
            }
        }
    }

    // ---------------- epilogue ----------------
    const float scale = (TERMS == 2) ? INV_WSCALE : 1.0f;
#pragma unroll
    for (int i = 0; i < 2; i++) {
        const int row0 = bm0 + wm * 32 + i * 16 + g;
        const int row1 = row0 + 8;
#pragma unroll
        for (int j = 0; j < 8; j++) {
            const int col = bn0 + wn * 64 + j * 8 + 2 * tig;
            float2 v01 = make_float2(acc[i][j][0] * scale, acc[i][j][1] * scale);
            float2 v23 = make_float2(acc[i][j][2] * scale, acc[i][j][3] * scale);
            if (EPI == 1) {
                float2 bb = *(const float2*)(bias + col);
                v01.x = fmaxf(v01.x + bb.x, 0.f); v01.y = fmaxf(v01.y + bb.y, 0.f);
                v23.x = fmaxf(v23.x + bb.x, 0.f); v23.y = fmaxf(v23.y + bb.y, 0.f);
            } else if (EPI == 2) {
                v01.x = fmaxf(v01.x, 0.f); v01.x *= v01.x;
                v01.y = fmaxf(v01.y, 0.f); v01.y *= v01.y;
                v23.x = fmaxf(v23.x, 0.f); v23.x *= v23.x;
                v23.y = fmaxf(v23.y, 0.f); v23.y *= v23.y;
            } else if (EPI == 3) {
                float2 r0v = *(const float2*)(R + (size_t)row0 * N + col);
                float2 r1v = *(const float2*)(R + (size_t)row1 * N + col);
                v01.x += r0v.x; v01.y += r0v.y;
                v23.x += r1v.x; v23.y += r1v.y;
            }
            if (OSPLIT) {
                __half2 h2;
                h2.x = __float2half(v01.x); h2.y = __float2half(v01.y);
                *(__half2*)(outh + (size_t)row0 * N + col) = h2;
                h2.x = __float2half(v23.x); h2.y = __float2half(v23.y);
                *(__half2*)(outh + (size_t)row1 * N + col) = h2;
            } else {
                *(float2*)(out + (size_t)row0 * N + col) = v01;
                *(float2*)(out + (size_t)row1 * N + col) = v23;
            }
        }
    }
}

// ---------------- meta-net layer 2 + sigmoid --------------------------------------
__global__ __launch_bounds__(256) void meta2_kernel(
    const float* __restrict__ hbuf, const float* __restrict__ Wm2,
    const float* __restrict__ bm2, float* __restrict__ sur)
{
    int idx = blockIdx.x * blockDim.x + threadIdx.x;
    if (idx >= MM * HH) return;
    int m = idx / HH, h = idx % HH;
    const float* hv = hbuf + (size_t)m * HID;
    const float* w  = Wm2 + (size_t)h * HID;
    float acc = bm2[h];
#pragma unroll 8
    for (int j = 0; j < HID; j++) acc += hv[j] * w[j];
    sur[idx] = 1.f / (1.f + expf(-acc));
}

// ---------------- gated linear-attention scan (fused qkv input) -------------------
#define NSTG 4
#define SUBT 4
#define SSTEP 148   // floats: k[64] q[64] v[16] g[1] pad[3]

__global__ __launch_bounds__(128) void scan_kernel(
    const float* __restrict__ qkv, const float* __restrict__ sur,
    __half* __restrict__ ysh)
{
    __shared__ float ring[NSTG][SUBT][SSTEP];

    const int bid = blockIdx.x;
    const int b   = bid / (HH * 4);
    const int rem = bid % (HH * 4);
    const int h   = rem >> 2;
    const int eq  = rem & 3;          // 16-column quarter
    const int tid = threadIdx.x;
    const int dg  = tid & 7;
    const int el  = tid >> 3;         // 0..15
    const int e   = eq * 16 + el;
    const int d0  = dg * 8;

    const size_t baseIn  = (size_t)b * TT * C3 + (size_t)h * DD;
    const size_t baseOut = (size_t)b * TT * CC + (size_t)h * DD;
    const size_t surBase = (size_t)b * TT * HH + h;

    float s[8];
#pragma unroll
    for (int i = 0; i < 8; i++) s[i] = 0.f;

    auto fill = [&](int stg, int t0) {
        for (int idx = tid; idx < 4 * 36 + 4; idx += 128) {
            if (idx < 144) {
                int st = idx / 36, c = idx % 36;
                int t = t0 + st;
                if (t < TT) {
                    size_t off = baseIn + (size_t)t * C3;
                    if (c < 16)
                        cp16(&ring[stg][st][c * 4], qkv + off + CC + c * 4);
                    else if (c < 32)
                        cp16(&ring[stg][st][64 + (c - 16) * 4], qkv + off + (c - 16) * 4);
                    else
                        cp16(&ring[stg][st][128 + (c - 32) * 4],
                             qkv + off + 2 * CC + eq * 16 + (c - 32) * 4);
                }
            } else {
                int st = idx - 144;
                int t = t0 + st;
                if (t < TT)
                    cp4(&ring[stg][st][144], sur + surBase + (size_t)t * HH);
            }
        }
    };

#pragma unroll
    for (int i = 0; i < NSTG; i++) {
        fill(i, i * SUBT);
        asm volatile("cp.async.commit_group;");
    }

    const int NB = TT / SUBT;
    for (int ib = 0; ib < NB; ib++) {
        asm volatile("cp.async.wait_group %0;" :: "n"(NSTG - 1));
        __syncthreads();
        const int stg = ib & (NSTG - 1);

#pragma unroll
        for (int st = 0; st < SUBT; st++) {
            const float* row = ring[stg][st];
            const float gt = row[144];
            const float ve = row[128 + el];
            const float dt = 1.f - gt;
            const float c  = gt * ve;
            float accum = 0.f;
#pragma unroll
            for (int i = 0; i < 8; i++) {
                float kv = row[d0 + i];
                float qv = row[64 + d0 + i];
                s[i] = s[i] * dt + c * kv;
                accum = fmaf(qv, s[i], accum);
            }
            accum += __shfl_xor_sync(0xFFFFFFFF, accum, 1);
            accum += __shfl_xor_sync(0xFFFFFFFF, accum, 2);
            accum += __shfl_xor_sync(0xFFFFFFFF, accum, 4);
            if (dg == 0) {
                const int t = ib * SUBT + st;
                ysh[baseOut + (size_t)t * CC + e] = __float2half(accum);
            }
        }
        __syncthreads();
        fill(stg, (ib + NSTG) * SUBT);
        asm volatile("cp.async.commit_group;");
    }
}

// ---------------- RMSNorm -> fp16 -------------------------------------------------
__global__ __launch_bounds__(256) void rmsnorm_kernel(
    const float* __restrict__ y, __half* __restrict__ ynh)
{
    const int row = blockIdx.x;
    const float* p = y + (size_t)row * CC;
    float ss = 0.f;
    for (int i = threadIdx.x; i < CC; i += 256) { float u = p[i]; ss += u * u; }

    __shared__ float red[8];
    for (int o = 16; o > 0; o >>= 1) ss += __shfl_xor_sync(0xFFFFFFFF, ss, o);
    if ((threadIdx.x & 31) == 0) red[threadIdx.x >> 5] = ss;
    __syncthreads();
    if (threadIdx.x < 8) {
        ss = red[threadIdx.x];
        for (int o = 4; o > 0; o >>= 1) ss += __shfl_xor_sync(0xFF, ss, o);
        if (threadIdx.x == 0) red[0] = ss;
    }
    __syncthreads();
    const float inv = rsqrtf(red[0] * (1.f / CC) + 1.1920928955078125e-07f);
    for (int i = threadIdx.x; i < CC; i += 256)
        ynh[(size_t)row * CC + i] = __float2half(p[i] * inv);
}

// ---------------- host driver -----------------------------------------------------
#define SYM(p, s) cudaGetSymbolAddress((void**)&p, s)

extern "C" void kernel_launch(void* const* d_in, const int* in_sizes, int n_in,
                              void* d_out, int out_size)
{
    const float* x     = (const float*)d_in[0];
    const float* Wq    = (const float*)d_in[1];
    const float* Wk    = (const float*)d_in[2];
    const float* Wv    = (const float*)d_in[3];
    const float* Wm1   = (const float*)d_in[4];
    const float* bm1   = (const float*)d_in[5];
    const float* Wm2   = (const float*)d_in[6];
    const float* bm2   = (const float*)d_in[7];
    const float* Wproj = (const float*)d_in[8];
    const float* Wfc   = (const float*)d_in[9];
    const float* Wcp   = (const float*)d_in[10];
    float* out = (float*)d_out;

    float *pqkv, *ph, *psur, *py;
    __half *pxh, *pysh, *pynh, *pffh;
    __half *pWqkvh, *pWm1h, *pWm1l, *pWph, *pWfh, *pWch;

    SYM(pqkv, g_qkv); SYM(ph, g_h); SYM(psur, g_sur); SYM(py, g_y);
    SYM(pxh, g_xh); SYM(pysh, g_ysh); SYM(pynh, g_ynh); SYM(pffh, g_ffh);
    SYM(pWqkvh, g_Wqkvh);
    SYM(pWm1h, g_Wm1h); SYM(pWm1l, g_Wm1l);
    SYM(pWph, g_Wph); SYM(pWfh, g_Wfh); SYM(pWch, g_Wch);

    cudaFuncSetAttribute(hgemm<0,0,1>, cudaFuncAttributeMaxDynamicSharedMemorySize, SMEM_B1);
    cudaFuncSetAttribute(hgemm<1,0,2>, cudaFuncAttributeMaxDynamicSharedMemorySize, SMEM_B2);
    cudaFuncSetAttribute(hgemm<2,1,1>, cudaFuncAttributeMaxDynamicSharedMemorySize, SMEM_B1);
    cudaFuncSetAttribute(hgemm<3,0,1>, cudaFuncAttributeMaxDynamicSharedMemorySize, SMEM_B1);

    dim3 thr(256);
    dim3 gQKV(C3  / BNW, MM / BM);   // 24 x 32 = 768 CTAs
    dim3 gC  (CC  / BNW, MM / BM);
    dim3 gH  (HID / BNW, MM / BM);
    dim3 gFF (FF  / BNW, MM / BM);

    // 0: x -> fp16
    conv_h_kernel<<<(MM * CC / 2 + 255) / 256, thr>>>(x, pxh, MM * CC / 2);
    // 1: fused QKV weight convert (1-term)
    conv_qkv_kernel<<<(3 * CC * CC / 2 + 255) / 256, thr>>>(Wq, Wk, Wv, pWqkvh);
    // 2: Wm1 split (scaled, 2-term — gate path stays accurate)
    split_w_kernel<<<(HID * CC / 2 + 255) / 256, thr>>>(Wm1, pWm1h, pWm1l, HID * CC / 2);

    // 3: fused QKV projection -> qkv fp32 (1-term)
    hgemm<0,0,1><<<gQKV, thr, SMEM_B1>>>(pxh, pWqkvh, nullptr, nullptr, nullptr,
                                         pqkv, nullptr, MM, C3, CC);

    // 4: meta net layer 1 (2-term)
    hgemm<1,0,2><<<gH, thr, SMEM_B2>>>(pxh, pWm1h, pWm1l, bm1, nullptr,
                                       ph, nullptr, MM, HID, CC);
    // 5: meta net layer 2 + sigmoid
    meta2_kernel<<<(MM * HH + 255) / 256, thr>>>(ph, Wm2, bm2, psur);

    // 6: gated linear-attention scan -> ys (fp16)
    scan_kernel<<<BB * HH * 4, 128>>>(pqkv, psur, pysh);

    // 7: fused remaining weight convert (all 1-term)
    {
        int tot = CC * CC / 2 + FF * CC / 2 + CC * FF / 2;
        conv_w3_kernel<<<(tot + 255) / 256, thr>>>(Wproj, Wfc, Wcp, pWph, pWfh, pWch);
    }

    // 8: output projection (fp32 y, needed for residual; 1-term)
    hgemm<0,0,1><<<gC, thr, SMEM_B1>>>(pysh, pWph, nullptr, nullptr, nullptr,
                                       py, nullptr, MM, CC, CC);

    // 9: RMSNorm -> yn (fp16)
    rmsnorm_kernel<<<MM, thr>>>(py, pynh);

    // 10: MLP up: ff = relu(yn Wfc^T)^2 (fp16; 1-term)
    hgemm<2,1,1><<<gFF, thr, SMEM_B1>>>(pynh, pWfh, nullptr, nullptr, nullptr,
                                        nullptr, pffh, MM, FF, CC);
    // 11: MLP down + residual: out = y + ff Wcp^T (1-term)
    hgemm<3,0,1><<<gC, thr, SMEM_B1>>>(pffh, pWch, nullptr, nullptr, py,
                                       out, nullptr, MM, CC, FF);
}

// round 17
// speedup vs baseline: 1.8966x; 1.0658x over previous
#include <cuda_runtime.h>
#include <cuda_fp16.h>
#include <stdint.h>
#include <math.h>

// Problem dims (fixed)
#define BB   2
#define TT   2048
#define CC   1024
#define HH   16
#define DD   64
#define HID  256
#define FF   4096
#define MM   (BB*TT)   // 4096 rows
#define C3   (3*CC)    // fused qkv width

#define WSCALE   32.0f
#define INV_WSCALE (1.0f/32.0f)

// ---------------- scratch (device globals; no allocation allowed) ----------------
__device__ __align__(16) float g_qkv[MM*C3];     // fused q|k|v fp32
__device__ __align__(16) float g_h [MM*HID];
__device__ __align__(16) float g_sur[MM*HH];
__device__ __align__(16) float g_y [MM*CC];
// fp16 activations
__device__ __align__(16) __half g_xh [MM*CC];
__device__ __align__(16) __half g_ysh[MM*CC];
__device__ __align__(16) __half g_ynh[MM*CC];
__device__ __align__(16) __half g_ffh[MM*FF];
// fp16 weights: 1-term for qkv/proj/fc/cp; 2-term (scaled hi/lo) for meta1 only
__device__ __align__(16) __half g_Wqkvh[C3*CC];
__device__ __align__(16) __half g_Wm1h[HID*CC], g_Wm1l[HID*CC];
__device__ __align__(16) __half g_Wph[CC*CC];
__device__ __align__(16) __half g_Wfh[FF*CC];
__device__ __align__(16) __half g_Wch[CC*FF];

// ---------------- helpers ---------------------------------------------------------
__device__ __forceinline__ void wsplit2(float v, __half& h, __half& l) {
    float vs = v * WSCALE;
    h = __float2half(vs);
    l = __float2half(vs - __half2float(h));
}

// fused prep: x -> fp16 | Wq|Wk|Wv -> fp16 concat | Wm1 -> scaled hi/lo
__global__ __launch_bounds__(256) void prep1_kernel(
    const float* __restrict__ x,
    const float* __restrict__ Wq, const float* __restrict__ Wk,
    const float* __restrict__ Wv, const float* __restrict__ Wm1,
    __half* __restrict__ xh, __half* __restrict__ Wqkvh,
    __half* __restrict__ Wm1h, __half* __restrict__ Wm1l)
{
    const int sx = MM * CC / 2;          // x float2 count
    const int sw = CC * CC / 2;          // per-qkv-weight float2 count
    const int sm1 = HID * CC / 2;
    int i = blockIdx.x * 256 + threadIdx.x;
    if (i < sx) {
        float2 v = ((const float2*)x)[i];
        __half2 h; h.x = __float2half(v.x); h.y = __float2half(v.y);
        ((__half2*)xh)[i] = h;
        return;
    }
    i -= sx;
    if (i < 3 * sw) {
        const float* src = (i < sw) ? Wq : (i < 2 * sw ? Wk : Wv);
        int j = (i < sw) ? i : (i < 2 * sw ? i - sw : i - 2 * sw);
        float2 v = ((const float2*)src)[j];
        __half2 h; h.x = __float2half(v.x); h.y = __float2half(v.y);
        ((__half2*)Wqkvh)[i] = h;
        return;
    }
    i -= 3 * sw;
    if (i < sm1) {
        float2 v = ((const float2*)Wm1)[i];
        __half2 h, l;
        wsplit2(v.x, h.x, l.x);
        wsplit2(v.y, h.y, l.y);
        ((__half2*)Wm1h)[i] = h;
        ((__half2*)Wm1l)[i] = l;
    }
}
#define PREP1_TOT (MM*CC/2 + 3*(CC*CC/2) + HID*CC/2)

// fused fp16 convert of Wproj, Wfc, Wcp (all 1-term)
__global__ __launch_bounds__(256) void conv_w3_kernel(
    const float* __restrict__ Wp, const float* __restrict__ Wf,
    const float* __restrict__ Wc,
    __half* __restrict__ Wph, __half* __restrict__ Wfh, __half* __restrict__ Wch)
{
    const int s1 = CC * CC / 2;
    const int s2 = FF * CC / 2;
    const int s3 = CC * FF / 2;
    int i = blockIdx.x * 256 + threadIdx.x;
    if (i >= s1 + s2 + s3) return;
    const float* src; __half* dst; int j;
    if (i < s1)           { src = Wp; dst = Wph; j = i; }
    else if (i < s1 + s2) { src = Wf; dst = Wfh; j = i - s1; }
    else                  { src = Wc; dst = Wch; j = i - s1 - s2; }
    float2 v = ((const float2*)src)[j];
    __half2 h; h.x = __float2half(v.x); h.y = __float2half(v.y);
    ((__half2*)dst)[j] = h;
}

__device__ __forceinline__ void cp16(void* dst, const void* src) {
    unsigned int d = (unsigned int)__cvta_generic_to_shared(dst);
    asm volatile("cp.async.cg.shared.global [%0], [%1], 16;" :: "r"(d), "l"(src));
}
__device__ __forceinline__ void cp4(void* dst, const void* src) {
    unsigned int d = (unsigned int)__cvta_generic_to_shared(dst);
    asm volatile("cp.async.ca.shared.global [%0], [%1], 4;" :: "r"(d), "l"(src));
}

__device__ __forceinline__ void mma16(float c[4], const uint32_t a[4],
                                      uint32_t b0, uint32_t b1) {
    asm volatile(
        "mma.sync.aligned.m16n8k16.row.col.f32.f16.f16.f32 "
        "{%0,%1,%2,%3},{%4,%5,%6,%7},{%8,%9},{%0,%1,%2,%3};"
        : "+f"(c[0]), "+f"(c[1]), "+f"(c[2]), "+f"(c[3])
        : "r"(a[0]), "r"(a[1]), "r"(a[2]), "r"(a[3]), "r"(b0), "r"(b1));
}

#define LDSM4(r, addr) \
    asm volatile("ldmatrix.sync.aligned.m8n8.x4.shared.b16 {%0,%1,%2,%3},[%4];" \
        : "=r"((r)[0]), "=r"((r)[1]), "=r"((r)[2]), "=r"((r)[3]) : "r"(addr))

// ---------------- fp16 tensor-core GEMM: out = epi( A @ W^T ) ---------------------
// TERMS=2: W pre-scaled hi/lo (x WSCALE), acc un-scaled in epilogue.
// TERMS=1: W plain fp16.
// EPI: 0 plain, 1 relu(acc+bias), 2 relu(acc)^2, 3 acc+R   OSPLIT: 0 fp32, 1 fp16
#define BM   128
#define BNW  128
#define BKH  64                // k elements per stage (doubled: amortize barriers)
#define STR  72                // padded smem row stride (halfs); conflict-free LDSM
#define STAGE_H (BM*STR)       // 9216 halfs per array per stage
#define SMEM_B2 (2*3*STAGE_H*2)   // 110592 B
#define SMEM_B1 (2*2*STAGE_H*2)   // 73728 B

template<int EPI, int OSPLIT, int TERMS>
__global__ __launch_bounds__(256, 2) void hgemm(
    const __half* __restrict__ Ah, const __half* __restrict__ Whg,
    const __half* __restrict__ Wlg,
    const float* __restrict__ bias, const float* __restrict__ R,
    float* __restrict__ out, __half* __restrict__ outh, int M, int N, int K)
{
    extern __shared__ __half sm[];
    const int NARR = (TERMS == 2) ? 3 : 2;
    const int tid  = threadIdx.x;
    const int lane = tid & 31;
    const int w    = tid >> 5;
    const int g    = lane >> 2;
    const int tig  = lane & 3;
    const int wm   = w & 3;          // 4 warps along M (32 rows)
    const int wn   = w >> 2;         // 2 warps along N (64 cols)
    const int bm0  = blockIdx.y * BM;
    const int bn0  = blockIdx.x * BNW;

    const uint32_t smb = (uint32_t)__cvta_generic_to_shared(sm);
    const uint32_t lofs = (uint32_t)(((lane & 7) + ((lane >> 3) & 1) * 8) * STR
                                     + (lane >> 4) * 8);

    float acc[2][8][4];
#pragma unroll
    for (int i = 0; i < 2; i++)
#pragma unroll
        for (int j = 0; j < 8; j++)
#pragma unroll
            for (int r = 0; r < 4; r++) acc[i][j][r] = 0.f;

    const int NK = K / BKH;

    // per array: 128 rows x 64 halfs = 1024 16B-chunks; 256 threads x 4
    auto load_stage = [&](int s, int k0) {
        __half* base = sm + s * NARR * STAGE_H;
#pragma unroll
        for (int t = 0; t < 4; t++) {
            int tsk = tid + t * 256;
            int row = tsk >> 3;
            int ch  = (tsk & 7) * 8;
            int so  = row * STR + ch;
            cp16(base + 0 * STAGE_H + so, Ah  + (size_t)(bm0 + row) * K + k0 + ch);
            cp16(base + 1 * STAGE_H + so, Whg + (size_t)(bn0 + row) * K + k0 + ch);
            if (TERMS == 2)
                cp16(base + 2 * STAGE_H + so, Wlg + (size_t)(bn0 + row) * K + k0 + ch);
        }
    };

    load_stage(0, 0);
    asm volatile("cp.async.commit_group;");

    for (int it = 0; it < NK; it++) {
        asm volatile("cp.async.wait_group 0;");
        __syncthreads();

        if (it + 1 < NK) {
            load_stage((it + 1) & 1, (it + 1) * BKH);
            asm volatile("cp.async.commit_group;");
        }

        const uint32_t stageB = smb + (uint32_t)((it & 1) * NARR * STAGE_H) * 2;

#pragma unroll
        for (int ks = 0; ks < BKH; ks += 16) {
            uint32_t ah[2][4];
#pragma unroll
            for (int i = 0; i < 2; i++) {
                uint32_t ta = stageB + 2u * ((uint32_t)((wm * 32 + i * 16) * STR + ks) + lofs);
                LDSM4(ah[i], ta);
            }
            // software-pipelined B fragments (ping-pong, one-jp lookahead)
            uint32_t bhv[2][4], blv[2][4];
            {
                uint32_t tb = stageB + 2u * ((uint32_t)(1 * STAGE_H + (wn * 64) * STR + ks) + lofs);
                LDSM4(bhv[0], tb);
                if (TERMS == 2) LDSM4(blv[0], tb + 2u * STAGE_H);
            }
#pragma unroll
            for (int jp = 0; jp < 4; jp++) {
                const int cur = jp & 1;
                if (jp < 3) {
                    uint32_t tb = stageB + 2u * ((uint32_t)(1 * STAGE_H
                                  + (wn * 64 + (jp + 1) * 16) * STR + ks) + lofs);
                    LDSM4(bhv[cur ^ 1], tb);
                    if (TERMS == 2) LDSM4(blv[cur ^ 1], tb + 2u * STAGE_H);
                }
#pragma unroll
                for (int sub = 0; sub < 2; sub++) {
                    const int j = jp * 2 + sub;
                    const uint32_t b0h = bhv[cur][sub], b1h = bhv[cur][sub + 2];
                    mma16(acc[0][j], ah[0], b0h, b1h);
                    mma16(acc[1][j], ah[1], b0h, b1h);
                    if (TERMS == 2) {
                        const uint32_t b0l = blv[cur][sub], b1l = blv[cur][sub + 2];
                        mma16(acc[0][j], ah[0], b0l, b1l);
                        mma16(acc[1][j], ah[1], b0l, b1l);
                    }
                }
            }
        }
    }

    // ---------------- epilogue ----------------
    const float scale = (TERMS == 2) ? INV_WSCALE : 1.0f;
#pragma unroll
    for (int i = 0; i < 2; i++) {
        const int row0 = bm0 + wm * 32 + i * 16 + g;
        const int row1 = row0 + 8;
#pragma unroll
        for (int j = 0; j < 8; j++) {
            const int col = bn0 + wn * 64 + j * 8 + 2 * tig;
            float2 v01 = make_float2(acc[i][j][0] * scale, acc[i][j][1] * scale);
            float2 v23 = make_float2(acc[i][j][2] * scale, acc[i][j][3] * scale);
            if (EPI == 1) {
                float2 bb = *(const float2*)(bias + col);
                v01.x = fmaxf(v01.x + bb.x, 0.f); v01.y = fmaxf(v01.y + bb.y, 0.f);
                v23.x = fmaxf(v23.x + bb.x, 0.f); v23.y = fmaxf(v23.y + bb.y, 0.f);
            } else if (EPI == 2) {
                v01.x = fmaxf(v01.x, 0.f); v01.x *= v01.x;
                v01.y = fmaxf(v01.y, 0.f); v01.y *= v01.y;
                v23.x = fmaxf(v23.x, 0.f); v23.x *= v23.x;
                v23.y = fmaxf(v23.y, 0.f); v23.y *= v23.y;
            } else if (EPI == 3) {
                float2 r0v = *(const float2*)(R + (size_t)row0 * N + col);
                float2 r1v = *(const float2*)(R + (size_t)row1 * N + col);
                v01.x += r0v.x; v01.y += r0v.y;
                v23.x += r1v.x; v23.y += r1v.y;
            }
            if (OSPLIT) {
                __half2 h2;
                h2.x = __float2half(v01.x); h2.y = __float2half(v01.y);
                *(__half2*)(outh + (size_t)row0 * N + col) = h2;
                h2.x = __float2half(v23.x); h2.y = __float2half(v23.y);
                *(__half2*)(outh + (size_t)row1 * N + col) = h2;
            } else {
                *(float2*)(out + (size_t)row0 * N + col) = v01;
                *(float2*)(out + (size_t)row1 * N + col) = v23;
            }
        }
    }
}

// ---------------- meta-net layer 2 + sigmoid --------------------------------------
__global__ __launch_bounds__(256) void meta2_kernel(
    const float* __restrict__ hbuf, const float* __restrict__ Wm2,
    const float* __restrict__ bm2, float* __restrict__ sur)
{
    int idx = blockIdx.x * blockDim.x + threadIdx.x;
    if (idx >= MM * HH) return;
    int m = idx / HH, h = idx % HH;
    const float* hv = hbuf + (size_t)m * HID;
    const float* w  = Wm2 + (size_t)h * HID;
    float acc = bm2[h];
#pragma unroll 8
    for (int j = 0; j < HID; j++) acc += hv[j] * w[j];
    sur[idx] = 1.f / (1.f + expf(-acc));
}

// ---------------- gated linear-attention scan (fused qkv input) -------------------
#define NSTG 4
#define SUBT 4
#define SSTEP 148   // floats: k[64] q[64] v[16] g[1] pad[3]

__global__ __launch_bounds__(128) void scan_kernel(
    const float* __restrict__ qkv, const float* __restrict__ sur,
    __half* __restrict__ ysh)
{
    __shared__ float ring[NSTG][SUBT][SSTEP];

    const int bid = blockIdx.x;
    const int b   = bid / (HH * 4);
    const int rem = bid % (HH * 4);
    const int h   = rem >> 2;
    const int eq  = rem & 3;          // 16-column quarter
    const int tid = threadIdx.x;
    const int dg  = tid & 7;
    const int el  = tid >> 3;         // 0..15
    const int e   = eq * 16 + el;
    const int d0  = dg * 8;

    const size_t baseIn  = (size_t)b * TT * C3 + (size_t)h * DD;
    const size_t baseOut = (size_t)b * TT * CC + (size_t)h * DD;
    const size_t surBase = (size_t)b * TT * HH + h;

    float s[8];
#pragma unroll
    for (int i = 0; i < 8; i++) s[i] = 0.f;

    auto fill = [&](int stg, int t0) {
        for (int idx = tid; idx < 4 * 36 + 4; idx += 128) {
            if (idx < 144) {
                int st = idx / 36, c = idx % 36;
                int t = t0 + st;
                if (t < TT) {
                    size_t off = baseIn + (size_t)t * C3;
                    if (c < 16)
                        cp16(&ring[stg][st][c * 4], qkv + off + CC + c * 4);
                    else if (c < 32)
                        cp16(&ring[stg][st][64 + (c - 16) * 4], qkv + off + (c - 16) * 4);
                    else
                        cp16(&ring[stg][st][128 + (c - 32) * 4],
                             qkv + off + 2 * CC + eq * 16 + (c - 32) * 4);
                }
            } else {
                int st = idx - 144;
                int t = t0 + st;
                if (t < TT)
                    cp4(&ring[stg][st][144], sur + surBase + (size_t)t * HH);
            }
        }
    };

#pragma unroll
    for (int i = 0; i < NSTG; i++) {
        fill(i, i * SUBT);
        asm volatile("cp.async.commit_group;");
    }

    const int NB = TT / SUBT;
    for (int ib = 0; ib < NB; ib++) {
        asm volatile("cp.async.wait_group %0;" :: "n"(NSTG - 1));
        __syncthreads();
        const int stg = ib & (NSTG - 1);

#pragma unroll
        for (int st = 0; st < SUBT; st++) {
            const float* row = ring[stg][st];
            const float gt = row[144];
            const float ve = row[128 + el];
            const float dt = 1.f - gt;
            const float c  = gt * ve;
            float accum = 0.f;
#pragma unroll
            for (int i = 0; i < 8; i++) {
                float kv = row[d0 + i];
                float qv = row[64 + d0 + i];
                s[i] = s[i] * dt + c * kv;
                accum = fmaf(qv, s[i], accum);
            }
            accum += __shfl_xor_sync(0xFFFFFFFF, accum, 1);
            accum += __shfl_xor_sync(0xFFFFFFFF, accum, 2);
            accum += __shfl_xor_sync(0xFFFFFFFF, accum, 4);
            if (dg == 0) {
                const int t = ib * SUBT + st;
                ysh[baseOut + (size_t)t * CC + e] = __float2half(accum);
            }
        }
        __syncthreads();
        fill(stg, (ib + NSTG) * SUBT);
        asm volatile("cp.async.commit_group;");
    }
}

// ---------------- RMSNorm -> fp16 -------------------------------------------------
__global__ __launch_bounds__(256) void rmsnorm_kernel(
    const float* __restrict__ y, __half* __restrict__ ynh)
{
    const int row = blockIdx.x;
    const float* p = y + (size_t)row * CC;
    float ss = 0.f;
    for (int i = threadIdx.x; i < CC; i += 256) { float u = p[i]; ss += u * u; }

    __shared__ float red[8];
    for (int o = 16; o > 0; o >>= 1) ss += __shfl_xor_sync(0xFFFFFFFF, ss, o);
    if ((threadIdx.x & 31) == 0) red[threadIdx.x >> 5] = ss;
    __syncthreads();
    if (threadIdx.x < 8) {
        ss = red[threadIdx.x];
        for (int o = 4; o > 0; o >>= 1) ss += __shfl_xor_sync(0xFF, ss, o);
        if (threadIdx.x == 0) red[0] = ss;
    }
    __syncthreads();
    const float inv = rsqrtf(red[0] * (1.f / CC) + 1.1920928955078125e-07f);
    for (int i = threadIdx.x; i < CC; i += 256)
        ynh[(size_t)row * CC + i] = __float2half(p[i] * inv);
}

// ---------------- host driver -----------------------------------------------------
#define SYM(p, s) cudaGetSymbolAddress((void**)&p, s)

extern "C" void kernel_launch(void* const* d_in, const int* in_sizes, int n_in,
                              void* d_out, int out_size)
{
    const float* x     = (const float*)d_in[0];
    const float* Wq    = (const float*)d_in[1];
    const float* Wk    = (const float*)d_in[2];
    const float* Wv    = (const float*)d_in[3];
    const float* Wm1   = (const float*)d_in[4];
    const float* bm1   = (const float*)d_in[5];
    const float* Wm2   = (const float*)d_in[6];
    const float* bm2   = (const float*)d_in[7];
    const float* Wproj = (const float*)d_in[8];
    const float* Wfc   = (const float*)d_in[9];
    const float* Wcp   = (const float*)d_in[10];
    float* out = (float*)d_out;

    float *pqkv, *ph, *psur, *py;
    __half *pxh, *pysh, *pynh, *pffh;
    __half *pWqkvh, *pWm1h, *pWm1l, *pWph, *pWfh, *pWch;

    SYM(pqkv, g_qkv); SYM(ph, g_h); SYM(psur, g_sur); SYM(py, g_y);
    SYM(pxh, g_xh); SYM(pysh, g_ysh); SYM(pynh, g_ynh); SYM(pffh, g_ffh);
    SYM(pWqkvh, g_Wqkvh);
    SYM(pWm1h, g_Wm1h); SYM(pWm1l, g_Wm1l);
    SYM(pWph, g_Wph); SYM(pWfh, g_Wfh); SYM(pWch, g_Wch);

    cudaFuncSetAttribute(hgemm<0,0,1>, cudaFuncAttributeMaxDynamicSharedMemorySize, SMEM_B1);
    cudaFuncSetAttribute(hgemm<1,0,2>, cudaFuncAttributeMaxDynamicSharedMemorySize, SMEM_B2);
    cudaFuncSetAttribute(hgemm<2,1,1>, cudaFuncAttributeMaxDynamicSharedMemorySize, SMEM_B1);
    cudaFuncSetAttribute(hgemm<3,0,1>, cudaFuncAttributeMaxDynamicSharedMemorySize, SMEM_B1);

    dim3 thr(256);
    dim3 gQKV(C3  / BNW, MM / BM);   // 24 x 32 = 768 CTAs
    dim3 gC  (CC  / BNW, MM / BM);
    dim3 gH  (HID / BNW, MM / BM);
    dim3 gFF (FF  / BNW, MM / BM);

    // 0: fused prep (x -> fp16, Wqkv -> fp16 concat, Wm1 -> scaled hi/lo)
    prep1_kernel<<<(PREP1_TOT + 255) / 256, thr>>>(x, Wq, Wk, Wv, Wm1,
                                                   pxh, pWqkvh, pWm1h, pWm1l);

    // 1: fused QKV projection -> qkv fp32 (1-term)
    hgemm<0,0,1><<<gQKV, thr, SMEM_B1>>>(pxh, pWqkvh, nullptr, nullptr, nullptr,
                                         pqkv, nullptr, MM, C3, CC);

    // 2: meta net layer 1 (2-term)
    hgemm<1,0,2><<<gH, thr, SMEM_B2>>>(pxh, pWm1h, pWm1l, bm1, nullptr,
                                       ph, nullptr, MM, HID, CC);
    // 3: meta net layer 2 + sigmoid
    meta2_kernel<<<(MM * HH + 255) / 256, thr>>>(ph, Wm2, bm2, psur);

    // 4: gated linear-attention scan -> ys (fp16)
    scan_kernel<<<BB * HH * 4, 128>>>(pqkv, psur, pysh);

    // 5: remaining weight convert (all 1-term)
    {
        int tot = CC * CC / 2 + FF * CC / 2 + CC * FF / 2;
        conv_w3_kernel<<<(tot + 255) / 256, thr>>>(Wproj, Wfc, Wcp, pWph, pWfh, pWch);
    }

    // 6: output projection (fp32 y, needed for residual; 1-term)
    hgemm<0,0,1><<<gC, thr, SMEM_B1>>>(pysh, pWph, nullptr, nullptr, nullptr,
                                       py, nullptr, MM, CC, CC);

    // 7: RMSNorm -> yn (fp16)
    rmsnorm_kernel<<<MM, thr>>>(py, pynh);

    // 8: MLP up: ff = relu(yn Wfc^T)^2 (fp16; 1-term)
    hgemm<2,1,1><<<gFF, thr, SMEM_B1>>>(pynh, pWfh, nullptr, nullptr, nullptr,
                                        nullptr, pffh, MM, FF, CC);
    // 9: MLP down + residual: out = y + ff Wcp^T (1-term)
    hgemm<3,0,1><<<gC, thr, SMEM_B1>>>(pffh, pWch, nullptr, nullptr, py,
                                       out, nullptr, MM, CC, FF);
}